// round 2
// baseline (speedup 1.0000x reference)
#include <cuda_runtime.h>

// ---------------------------------------------------------------------------
// BigBird transformer block, fp32, sm_103a.
// Pipeline: 3x SGEMM (QKV, head-layout epilogue) -> sparse attention -> SGEMM
// (output proj + bias). Inner loops use packed fma.rn.f32x2 (FFMA2) which
// ptxas never emits from C++ but doubles fp32 throughput on B300.
// ---------------------------------------------------------------------------

namespace {
constexpr int Bn    = 2;
constexpr int Sn    = 4096;
constexpr int Dn    = 1024;
constexpr int Hn    = 16;
constexpr int DHn   = 64;
constexpr int NBn   = 64;   // S / BLK
constexpr int NGn   = 2;    // global blocks (g=128 / 64)
constexpr int NMIDn = 60;   // NB - NG - 2
constexpr int Mrows = Bn * Sn;           // 8192
constexpr int ATTN_SMEM = 4 * 64 * 68 * 4;  // qsT,ksT,vs,psT  = 69632 B
}

__device__ float g_q  [Bn * Hn * Sn * DHn];
__device__ float g_k  [Bn * Hn * Sn * DHn];
__device__ float g_v  [Bn * Hn * Sn * DHn];
__device__ float g_ctx[Bn * Sn * Dn];

// ---- packed f32x2 helpers (Blackwell-only FFMA2 path) ----------------------
__device__ __forceinline__ unsigned long long bcast2(float x) {
    unsigned long long r;
    asm("mov.b64 %0, {%1, %1};" : "=l"(r) : "f"(x));
    return r;
}
__device__ __forceinline__ void fma2(unsigned long long& d,
                                     unsigned long long a,
                                     unsigned long long b) {
    asm("fma.rn.f32x2 %0, %1, %2, %0;" : "+l"(d) : "l"(a), "l"(b));
}
__device__ __forceinline__ void mul2(unsigned long long& d, unsigned long long a) {
    asm("mul.rn.f32x2 %0, %0, %1;" : "+l"(d) : "l"(a));
}
__device__ __forceinline__ void unpack2(float& lo, float& hi, unsigned long long v) {
    asm("mov.b64 {%0, %1}, %2;" : "=f"(lo), "=f"(hi) : "l"(v));
}

// ---------------------------------------------------------------------------
// SGEMM: C[8192 x 1024] = A[8192 x 1024] @ W[1024 x 1024]
// MODE 0: C[r*1024+c] = acc + bias[c]          (output projection -> d_out)
// MODE 1: scatter to head layout [b,h,s,e]     (q/k/v)
// 128x128 CTA tile, BK=8, 256 threads, 8x8 per thread (8 x 4 f32x2 pairs).
// ---------------------------------------------------------------------------
template <int MODE>
__global__ __launch_bounds__(256, 2)
void sgemm_k(const float* __restrict__ A, const float* __restrict__ W,
             float* __restrict__ Cout, const float* __restrict__ bias)
{
    __shared__ float As[8][132];   // transposed A tile, +4 pad (store conflicts)
    __shared__ float Bs[8][132];

    const int t  = threadIdx.x;
    const int tx = t & 15, ty = t >> 4;
    const int n0 = blockIdx.x << 7;
    const int m0 = blockIdx.y << 7;

    const int arow = t >> 1, ak = (t & 1) << 2;
    const int bk   = t >> 5, bc = (t & 31) << 2;
    const float* Ap = A + (size_t)(m0 + arow) * Dn + ak;
    const float* Bp = W + (size_t)bk * Dn + n0 + bc;

    float4 aReg = *(const float4*)Ap;
    float4 bReg = *(const float4*)Bp;

    unsigned long long acc[8][4];
#pragma unroll
    for (int i = 0; i < 8; i++)
#pragma unroll
        for (int j = 0; j < 4; j++) acc[i][j] = 0ull;

    constexpr int NKT = Dn / 8;
    for (int kt = 0; kt < NKT; ++kt) {
        As[ak + 0][arow] = aReg.x;
        As[ak + 1][arow] = aReg.y;
        As[ak + 2][arow] = aReg.z;
        As[ak + 3][arow] = aReg.w;
        *(float4*)&Bs[bk][bc] = bReg;
        __syncthreads();
        if (kt + 1 < NKT) {
            aReg = *(const float4*)(Ap + (kt + 1) * 8);
            bReg = *(const float4*)(Bp + (size_t)(kt + 1) * 8 * Dn);
        }
#pragma unroll
        for (int kk = 0; kk < 8; kk++) {
            float4 a0 = *(const float4*)&As[kk][ty * 8];
            float4 a1 = *(const float4*)&As[kk][ty * 8 + 4];
            ulonglong2 b0 = *(const ulonglong2*)&Bs[kk][tx * 8];
            ulonglong2 b1 = *(const ulonglong2*)&Bs[kk][tx * 8 + 4];
            float av[8] = {a0.x, a0.y, a0.z, a0.w, a1.x, a1.y, a1.z, a1.w};
            unsigned long long bv[4] = {b0.x, b0.y, b1.x, b1.y};
#pragma unroll
            for (int i = 0; i < 8; i++) {
                unsigned long long ap = bcast2(av[i]);
#pragma unroll
                for (int j = 0; j < 4; j++) fma2(acc[i][j], ap, bv[j]);
            }
        }
        __syncthreads();
    }

#pragma unroll
    for (int i = 0; i < 8; i++) {
        const int r = m0 + ty * 8 + i;
        float o[8];
#pragma unroll
        for (int j = 0; j < 4; j++) unpack2(o[2 * j], o[2 * j + 1], acc[i][j]);
        const int c = n0 + tx * 8;
        if (MODE == 0) {
#pragma unroll
            for (int j = 0; j < 8; j++) o[j] += bias[c + j];
            *(float4*)&Cout[(size_t)r * Dn + c]     = make_float4(o[0], o[1], o[2], o[3]);
            *(float4*)&Cout[(size_t)r * Dn + c + 4] = make_float4(o[4], o[5], o[6], o[7]);
        } else {
            const int b = r >> 12;            // r / S
            const int s = r & (Sn - 1);
            const int h = c >> 6;             // 8 consecutive cols stay in one head
            const int e = c & 63;
            float* dst = Cout + ((size_t)(b * Hn + h) * Sn + s) * DHn + e;
            *(float4*)dst       = make_float4(o[0], o[1], o[2], o[3]);
            *(float4*)(dst + 4) = make_float4(o[4], o[5], o[6], o[7]);
        }
    }
}

// ---------------------------------------------------------------------------
// Sparse BigBird attention. One CTA per (query block, b, h); 2048 CTAs.
// Flash-style online softmax over 64-key tiles.
//   jb <  2 : all 4096 keys (to_mask)           -> 64 tiles   [scheduled first]
//   jb == 2 : keys [0,320)  (to_mask)           -> 5 tiles
//   jb == 63: keys [0,128) + [S-192,S) (to_mask)-> 5 tiles
//   else    : keys [0,128) (to_mask) + band 192 (band_mask) -> 5 tiles
// 256 threads; thread = (ty=row/4, tx=key/4) computing a 4x4 patch.
// ---------------------------------------------------------------------------
__global__ __launch_bounds__(256)
void attn_k(const float* __restrict__ to_mask,
            const float* __restrict__ band_mask,
            const float* __restrict__ from_mask)
{
    extern __shared__ float sm[];
    constexpr int SP = 68;
    float* qsT = sm;                 // [e][row]
    float* ksT = sm + 64 * SP;       // [e][key]
    float* vs  = sm + 2 * 64 * SP;   // [key][col]
    float* psT = sm + 3 * 64 * SP;   // [key][row]

    const int idx = blockIdx.x;
    const int jb  = idx >> 5;        // / (B*H) -> global blocks (jb 0,1) first
    const int bh  = idx & 31;
    const int b   = bh >> 4, h = bh & 15;

    const int t  = threadIdx.x;
    const int tx = t & 15, ty = t >> 4;

    const float* qg    = g_q + ((size_t)(b * Hn + h) * Sn + jb * 64) * DHn;
    const float* kbase = g_k + (size_t)(b * Hn + h) * Sn * DHn;
    const float* vbase = g_v + (size_t)(b * Hn + h) * Sn * DHn;

    // load q tile, transposed into qsT[e][row]
    for (int i = t; i < 64 * 16; i += 256) {
        const int row = i >> 4;
        const int e4  = (i & 15) << 2;
        float4 qv = *(const float4*)(qg + row * 64 + e4);
        qsT[(e4 + 0) * SP + row] = qv.x;
        qsT[(e4 + 1) * SP + row] = qv.y;
        qsT[(e4 + 2) * SP + row] = qv.z;
        qsT[(e4 + 3) * SP + row] = qv.w;
    }

    float mrow[4], lrow[4];
    unsigned long long acc[4][2];
#pragma unroll
    for (int i = 0; i < 4; i++) {
        mrow[i] = -1e30f; lrow[i] = 0.f;
        acc[i][0] = 0ull; acc[i][1] = 0ull;
    }

    const int ntiles = (jb < NGn) ? 64 : 5;
    const float rs = 0.125f;  // 1/sqrt(64)

    for (int kt = 0; kt < ntiles; ++kt) {
        int kb, mtype = 0, kc0 = 0;
        if (jb < NGn)            { kb = kt * 64; }
        else if (jb == NGn)      { kb = kt * 64; }
        else if (jb == NBn - 1)  { kb = (kt < 2) ? kt * 64 : (Sn - 192 + (kt - 2) * 64); }
        else {
            if (kt < 2)          { kb = kt * 64; }
            else { kb = (jb - 1) * 64 + (kt - 2) * 64; mtype = 1; kc0 = (kt - 2) * 64; }
        }

        __syncthreads();  // previous tile fully consumed
        const float* kp = kbase + (size_t)kb * 64;
        const float* vp = vbase + (size_t)kb * 64;
        for (int i = t; i < 64 * 16; i += 256) {
            const int key = i >> 4;
            const int e4  = (i & 15) << 2;
            float4 kv = *(const float4*)(kp + key * 64 + e4);
            ksT[(e4 + 0) * SP + key] = kv.x;
            ksT[(e4 + 1) * SP + key] = kv.y;
            ksT[(e4 + 2) * SP + key] = kv.z;
            ksT[(e4 + 3) * SP + key] = kv.w;
            *(float4*)&vs[key * SP + e4] = *(const float4*)(vp + key * 64 + e4);
        }
        __syncthreads();

        // --- scores: s[i][j] = q_row . k_key -------------------------------
        unsigned long long s2[4][2];
#pragma unroll
        for (int i = 0; i < 4; i++) { s2[i][0] = 0ull; s2[i][1] = 0ull; }
#pragma unroll 8
        for (int e = 0; e < 64; e++) {
            float4 qf = *(const float4*)&qsT[e * SP + ty * 4];
            ulonglong2 kf = *(const ulonglong2*)&ksT[e * SP + tx * 4];
            float qa[4] = {qf.x, qf.y, qf.z, qf.w};
#pragma unroll
            for (int i = 0; i < 4; i++) {
                unsigned long long qq = bcast2(qa[i]);
                fma2(s2[i][0], qq, kf.x);
                fma2(s2[i][1], qq, kf.y);
            }
        }
        float s[4][4];
#pragma unroll
        for (int i = 0; i < 4; i++) {
            unpack2(s[i][0], s[i][1], s2[i][0]);
            unpack2(s[i][2], s[i][3], s2[i][1]);
        }

        // --- scale + mask penalty ------------------------------------------
        if (mtype == 0) {
            float pen[4];
#pragma unroll
            for (int j = 0; j < 4; j++)
                pen[j] = (1.0f - to_mask[b * Sn + kb + tx * 4 + j]) * -10000.0f;
#pragma unroll
            for (int i = 0; i < 4; i++)
#pragma unroll
                for (int j = 0; j < 4; j++) s[i][j] = s[i][j] * rs + pen[j];
        } else {
            const int m_idx = jb - (NGn + 1);
            const float* bm = band_mask + ((size_t)(b * NMIDn + m_idx) * 64) * 192;
#pragma unroll
            for (int i = 0; i < 4; i++) {
                const int qi = ty * 4 + i;
#pragma unroll
                for (int j = 0; j < 4; j++) {
                    const int kc = kc0 + tx * 4 + j;
                    s[i][j] = s[i][j] * rs + (1.0f - bm[qi * 192 + kc]) * -10000.0f;
                }
            }
        }

        // --- online softmax update -----------------------------------------
        float tmax[4];
#pragma unroll
        for (int i = 0; i < 4; i++)
            tmax[i] = fmaxf(fmaxf(s[i][0], s[i][1]), fmaxf(s[i][2], s[i][3]));
#pragma unroll
        for (int off = 8; off >= 1; off >>= 1)
#pragma unroll
            for (int i = 0; i < 4; i++)
                tmax[i] = fmaxf(tmax[i], __shfl_xor_sync(0xffffffffu, tmax[i], off));

        float rsum[4];
#pragma unroll
        for (int i = 0; i < 4; i++) {
            const float nm   = fmaxf(mrow[i], tmax[i]);
            const float corr = __expf(mrow[i] - nm);
            mrow[i] = nm;
            lrow[i] *= corr;
            unsigned long long c2 = bcast2(corr);
            mul2(acc[i][0], c2);
            mul2(acc[i][1], c2);
            float rsi = 0.f;
#pragma unroll
            for (int j = 0; j < 4; j++) {
                const float p = __expf(s[i][j] - nm);
                s[i][j] = p;
                rsi += p;
            }
            rsum[i] = rsi;
        }
#pragma unroll
        for (int off = 8; off >= 1; off >>= 1)
#pragma unroll
            for (int i = 0; i < 4; i++)
                rsum[i] += __shfl_xor_sync(0xffffffffu, rsum[i], off);
#pragma unroll
        for (int i = 0; i < 4; i++) lrow[i] += rsum[i];

        // stage probabilities transposed: psT[key][row]
#pragma unroll
        for (int j = 0; j < 4; j++)
#pragma unroll
            for (int i = 0; i < 4; i++)
                psT[(tx * 4 + j) * SP + ty * 4 + i] = s[i][j];
        __syncthreads();

        // --- PV accumulation -----------------------------------------------
#pragma unroll 8
        for (int key = 0; key < 64; key++) {
            float4 pf = *(const float4*)&psT[key * SP + ty * 4];
            ulonglong2 vf = *(const ulonglong2*)&vs[key * SP + tx * 4];
            float pa[4] = {pf.x, pf.y, pf.z, pf.w};
#pragma unroll
            for (int i = 0; i < 4; i++) {
                unsigned long long pp = bcast2(pa[i]);
                fma2(acc[i][0], pp, vf.x);
                fma2(acc[i][1], pp, vf.y);
            }
        }
    }

    // --- epilogue: normalize, apply from_mask, write ctx [b,s,h*64+e] -------
#pragma unroll
    for (int i = 0; i < 4; i++) {
        const int srow = jb * 64 + ty * 4 + i;
        const float fm = from_mask[b * Sn + srow];
        const float sc = fm / lrow[i];
        float o0, o1, o2, o3;
        unpack2(o0, o1, acc[i][0]);
        unpack2(o2, o3, acc[i][1]);
        *(float4*)&g_ctx[(size_t)(b * Sn + srow) * Dn + h * 64 + tx * 4] =
            make_float4(o0 * sc, o1 * sc, o2 * sc, o3 * sc);
    }
}

// ---------------------------------------------------------------------------
extern "C" void kernel_launch(void* const* d_in, const int* in_sizes, int n_in,
                              void* d_out, int out_size)
{
    const float* tokens    = (const float*)d_in[0];
    const float* band_mask = (const float*)d_in[1];
    const float* from_mask = (const float*)d_in[2];
    const float* to_mask   = (const float*)d_in[3];
    const float* Wq        = (const float*)d_in[4];
    const float* Wk        = (const float*)d_in[5];
    const float* Wv        = (const float*)d_in[6];
    const float* Wu        = (const float*)d_in[7];
    const float* bu        = (const float*)d_in[8];
    (void)in_sizes; (void)n_in; (void)out_size;

    float *qp = nullptr, *kp = nullptr, *vp = nullptr, *ctxp = nullptr;
    cudaGetSymbolAddress((void**)&qp,   g_q);
    cudaGetSymbolAddress((void**)&kp,   g_k);
    cudaGetSymbolAddress((void**)&vp,   g_v);
    cudaGetSymbolAddress((void**)&ctxp, g_ctx);

    cudaFuncSetAttribute(attn_k, cudaFuncAttributeMaxDynamicSharedMemorySize,
                         ATTN_SMEM);

    dim3 grid(Dn / 128, Mrows / 128);   // (8, 64)
    sgemm_k<1><<<grid, 256>>>(tokens, Wq, qp, nullptr);
    sgemm_k<1><<<grid, 256>>>(tokens, Wk, kp, nullptr);
    sgemm_k<1><<<grid, 256>>>(tokens, Wv, vp, nullptr);
    attn_k<<<Bn * Hn * NBn, 256, ATTN_SMEM>>>(to_mask, band_mask, from_mask);
    sgemm_k<0><<<grid, 256>>>(ctxp, Wu, (float*)d_out, bu);
}

// round 4
// speedup vs baseline: 1.6741x; 1.6741x over previous
#include <cuda_runtime.h>
#include <cuda_bf16.h>
#include <cstdint>

// ---------------------------------------------------------------------------
// BigBird transformer block on sm_103 (harness targets non-'a' sm_103: no
// tcgen05/TMEM). GEMMs use warp-level mma.sync bf16 (HMMA on the tensor pipe)
// with hi/lo split: D = Ah.Bh + Al.Bh + Ah.Bl  (error ~2^-16).
//   - fused QKV GEMM: [8192 x 3072] = tokens @ [Wq|Wk|Wv], head-layout scatter
//   - output GEMM:    d_out = ctx @ Wu + bu
// Attention: fp32 FFMA2 flash kernel (proven in R2); epilogue emits ctx as
// bf16 hi/lo so the output GEMM needs no extra conversion pass.
// ---------------------------------------------------------------------------

namespace {
constexpr int Bn    = 2;
constexpr int Sn    = 4096;
constexpr int Dn    = 1024;
constexpr int Hn    = 16;
constexpr int DHn   = 64;
constexpr int NBn   = 64;
constexpr int NGn   = 2;
constexpr int NMIDn = 60;
constexpr int Mrows = Bn * Sn;              // 8192
constexpr int ATTN_SMEM = 4 * 64 * 68 * 4;  // 69632 B

// HMMA GEMM tiling
constexpr int BK      = 32;                  // k-chunk (bf16 elems)
constexpr int NCHUNK  = Dn / BK;             // 32
constexpr int ROWB    = 80;                  // padded row bytes (32 bf16 -> 80B)
constexpr int MATB    = 128 * ROWB;          // 10240 B per matrix tile
constexpr int STG     = 4 * MATB;            // Ah,Al,Bh,Bl = 40960 B per stage
constexpr int NSTG    = 3;
constexpr int GEMM_SMEM = NSTG * STG;        // 122880 B
}

// ---- scratch (device globals: no allocations allowed) ----------------------
__device__ float g_q[Bn * Hn * Sn * DHn];
__device__ float g_k[Bn * Hn * Sn * DHn];
__device__ float g_v[Bn * Hn * Sn * DHn];
__device__ __nv_bfloat16 g_Ahi[Mrows * Dn],      g_Alo[Mrows * Dn];
__device__ __nv_bfloat16 g_Bqkv_hi[3 * Dn * Dn], g_Bqkv_lo[3 * Dn * Dn];
__device__ __nv_bfloat16 g_Bu_hi[Dn * Dn],       g_Bu_lo[Dn * Dn];
__device__ __nv_bfloat16 g_Chi[Mrows * Dn],      g_Clo[Mrows * Dn];

// ---------------------------------------------------------------------------
// PTX helpers (all sm_80/90-era: valid under .target sm_103)
// ---------------------------------------------------------------------------
__device__ __forceinline__ uint32_t smem_u32(const void* p) {
    uint32_t a;
    asm("{ .reg .u64 t; cvta.to.shared.u64 t, %1; cvt.u32.u64 %0, t; }" : "=r"(a) : "l"(p));
    return a;
}
__device__ __forceinline__ void cpa16(uint32_t dst, const void* src) {
    asm volatile("cp.async.cg.shared.global [%0], [%1], 16;" :: "r"(dst), "l"(src));
}
__device__ __forceinline__ void cpa_commit() {
    asm volatile("cp.async.commit_group;" ::: "memory");
}
template <int N>
__device__ __forceinline__ void cpa_wait() {
    asm volatile("cp.async.wait_group %0;" :: "n"(N) : "memory");
}
__device__ __forceinline__ void ldm4(uint32_t* r, uint32_t addr) {
    asm volatile("ldmatrix.sync.aligned.m8n8.x4.shared.b16 {%0,%1,%2,%3}, [%4];"
                 : "=r"(r[0]), "=r"(r[1]), "=r"(r[2]), "=r"(r[3]) : "r"(addr));
}
__device__ __forceinline__ void mma16816(float* c, const uint32_t* a,
                                         uint32_t b0, uint32_t b1) {
    asm volatile(
        "mma.sync.aligned.m16n8k16.row.col.f32.bf16.bf16.f32 "
        "{%0,%1,%2,%3}, {%4,%5,%6,%7}, {%8,%9}, {%0,%1,%2,%3};"
        : "+f"(c[0]), "+f"(c[1]), "+f"(c[2]), "+f"(c[3])
        : "r"(a[0]), "r"(a[1]), "r"(a[2]), "r"(a[3]), "r"(b0), "r"(b1));
}

// ---- fp32 packed helpers (attention) ---------------------------------------
__device__ __forceinline__ unsigned long long bcast2(float x) {
    unsigned long long r;
    asm("mov.b64 %0, {%1, %1};" : "=l"(r) : "f"(x));
    return r;
}
__device__ __forceinline__ void fma2(unsigned long long& d, unsigned long long a,
                                     unsigned long long b) {
    asm("fma.rn.f32x2 %0, %1, %2, %0;" : "+l"(d) : "l"(a), "l"(b));
}
__device__ __forceinline__ void mul2(unsigned long long& d, unsigned long long a) {
    asm("mul.rn.f32x2 %0, %0, %1;" : "+l"(d) : "l"(a));
}
__device__ __forceinline__ void unpack2(float& lo, float& hi, unsigned long long v) {
    asm("mov.b64 {%0, %1}, %2;" : "=f"(lo), "=f"(hi) : "l"(v));
}
__device__ __forceinline__ void bsplit(float v, __nv_bfloat16& h, __nv_bfloat16& l) {
    h = __float2bfloat16(v);
    l = __float2bfloat16(v - __bfloat162float(h));
}

// ---------------------------------------------------------------------------
// prep: fp32 -> bf16 hi/lo split (tokens)
// ---------------------------------------------------------------------------
__global__ void split_k(const float* __restrict__ X,
                        __nv_bfloat16* __restrict__ Hi,
                        __nv_bfloat16* __restrict__ Lo, int n4)
{
    for (int i = blockIdx.x * blockDim.x + threadIdx.x; i < n4;
         i += gridDim.x * blockDim.x) {
        float4 v = ((const float4*)X)[i];
        __nv_bfloat16 h0, h1, h2, h3, l0, l1, l2, l3;
        bsplit(v.x, h0, l0); bsplit(v.y, h1, l1);
        bsplit(v.z, h2, l2); bsplit(v.w, h3, l3);
        __nv_bfloat162 a, b;
        a.x = h0; a.y = h1; b.x = h2; b.y = h3;
        *(__nv_bfloat162*)(Hi + 4 * i)     = a;
        *(__nv_bfloat162*)(Hi + 4 * i + 2) = b;
        a.x = l0; a.y = l1; b.x = l2; b.y = l3;
        *(__nv_bfloat162*)(Lo + 4 * i)     = a;
        *(__nv_bfloat162*)(Lo + 4 * i + 2) = b;
    }
}

// ---------------------------------------------------------------------------
// prep: W [K=1024, N=1024] fp32 -> B [N, K] bf16 hi/lo (transpose + split)
// ---------------------------------------------------------------------------
__global__ void packW_k(const float* __restrict__ W,
                        __nv_bfloat16* __restrict__ Bhi,
                        __nv_bfloat16* __restrict__ Blo, int nOff)
{
    __shared__ float tile[32][33];
    const int tx = threadIdx.x, ty = threadIdx.y;
    const int n0 = blockIdx.x * 32, k0 = blockIdx.y * 32;
#pragma unroll
    for (int j = 0; j < 4; j++)
        tile[ty + j * 8][tx] = W[(size_t)(k0 + ty + j * 8) * Dn + n0 + tx];
    __syncthreads();
    const int kk = k0 + tx;
#pragma unroll
    for (int j = 0; j < 4; j++) {
        const int n = n0 + ty + j * 8;
        __nv_bfloat16 h, l;
        bsplit(tile[tx][ty + j * 8], h, l);
        Bhi[(size_t)(nOff + n) * Dn + kk] = h;
        Blo[(size_t)(nOff + n) * Dn + kk] = l;
    }
}

// ---------------------------------------------------------------------------
// HMMA GEMM: D[M x Ntot] = A[M x 1024] @ B^T   (B stored [Ntot,1024] K-major)
// 128x128 CTA tile, 8 warps in 2x4 (64x32 per warp), BK=32, 3-stage cp.async.
// MODE 1: scatter to q/k/v head layout (Ntot = 3072, mat = n >> 10)
// MODE 0: d_out[r*1024 + n] = D + bias[n]
// ---------------------------------------------------------------------------
template <int MODE>
__global__ void __launch_bounds__(256)
hmma_gemm(const __nv_bfloat16* __restrict__ Ahi, const __nv_bfloat16* __restrict__ Alo,
          const __nv_bfloat16* __restrict__ Bhi, const __nv_bfloat16* __restrict__ Blo,
          const float* __restrict__ bias, float* __restrict__ Cout,
          float* __restrict__ Qo, float* __restrict__ Ko, float* __restrict__ Vo)
{
    extern __shared__ char smem[];
    const uint32_t sb = smem_u32(smem);
    const int t    = threadIdx.x;
    const int lane = t & 31;
    const int wid  = t >> 5;
    const int wm   = (wid & 1) << 6;    // warp m offset: 0 / 64
    const int wn   = (wid >> 1) << 5;   // warp n offset: 0/32/64/96
    const int m0   = blockIdx.y << 7;
    const int n0   = blockIdx.x << 7;

    // per-thread cp.async source/dest precompute: 2048 16B chunks per stage
    // idx = t + j*256; mat = idx>>9; rr = (idx>>2)&127; cc = idx&3
    auto load_stage = [&](int kc, int s) {
        const int kel = kc * BK;
        const uint32_t stb = sb + s * STG;
#pragma unroll
        for (int j = 0; j < 8; j++) {
            const int idx = t + (j << 8);
            const int mat = idx >> 9;
            const int rr  = (idx >> 2) & 127;
            const int cc  = idx & 3;
            const __nv_bfloat16* src;
            if (mat < 2)
                src = (mat ? Alo : Ahi) + (size_t)(m0 + rr) * Dn + kel + (cc << 3);
            else
                src = (mat == 2 ? Bhi : Blo) + (size_t)(n0 + rr) * Dn + kel + (cc << 3);
            cpa16(stb + mat * MATB + rr * ROWB + (cc << 4), src);
        }
        cpa_commit();
    };

    float acc[4][4][4];
#pragma unroll
    for (int i = 0; i < 4; i++)
#pragma unroll
        for (int j = 0; j < 4; j++)
#pragma unroll
            for (int q = 0; q < 4; q++) acc[i][j][q] = 0.f;

    load_stage(0, 0);
    load_stage(1, 1);

    for (int kc = 0; kc < NCHUNK; ++kc) {
        cpa_wait<1>();
        __syncthreads();
        const uint32_t stb = sb + (kc % 3) * STG;

#pragma unroll
        for (int k16 = 0; k16 < 2; k16++) {
            // A fragments: 4 m-tiles x (hi, lo)
            uint32_t ah[16], al[16];
            const uint32_t abase = stb + (wm + (lane & 15)) * ROWB +
                                   (k16 << 5) + ((lane >> 4) << 4);
#pragma unroll
            for (int mt = 0; mt < 4; mt++) {
                ldm4(ah + 4 * mt, abase + mt * 16 * ROWB);
                ldm4(al + 4 * mt, abase + mt * 16 * ROWB + MATB);
            }
#pragma unroll
            for (int ng = 0; ng < 2; ng++) {
                uint32_t bh[4], bl[4];
                const uint32_t bbase = stb + 2 * MATB +
                                       (wn + ng * 16 + (lane & 15)) * ROWB +
                                       (k16 << 5) + ((lane >> 4) << 4);
                ldm4(bh, bbase);
                ldm4(bl, bbase + MATB);
                // b frag (n8 first) = {r0, r2}; (n8 second) = {r1, r3}
#pragma unroll
                for (int mt = 0; mt < 4; mt++) {
#pragma unroll
                    for (int nn = 0; nn < 2; nn++) {
                        float* c = acc[mt][ng * 2 + nn];
                        const uint32_t b0 = nn ? bh[1] : bh[0];
                        const uint32_t b1 = nn ? bh[3] : bh[2];
                        const uint32_t lb0 = nn ? bl[1] : bl[0];
                        const uint32_t lb1 = nn ? bl[3] : bl[2];
                        mma16816(c, ah + 4 * mt, b0, b1);   // Ah.Bh
                        mma16816(c, al + 4 * mt, b0, b1);   // Al.Bh
                        mma16816(c, ah + 4 * mt, lb0, lb1); // Ah.Bl
                    }
                }
            }
        }
        if (kc + 2 < NCHUNK) load_stage(kc + 2, (kc + 2) % 3);
    }

    // ---- epilogue: c frag: row = l>>2 (+8), col = (l&3)*2 (+1) -------------
    const int rbase = m0 + wm + (lane >> 2);
    const int cbase = (lane & 3) << 1;
#pragma unroll
    for (int mt = 0; mt < 4; mt++) {
#pragma unroll
        for (int nf = 0; nf < 4; nf++) {
            const int n = n0 + wn + ((nf >> 1) << 4) + ((nf & 1) << 3) + cbase;
            const float* c = acc[mt][nf];
#pragma unroll
            for (int half = 0; half < 2; half++) {
                const int r = rbase + mt * 16 + half * 8;
                const float v0 = c[2 * half], v1 = c[2 * half + 1];
                if (MODE == 0) {
                    *(float2*)&Cout[(size_t)r * Dn + n] =
                        make_float2(v0 + bias[n], v1 + bias[n + 1]);
                } else {
                    const int mat = n >> 10;
                    const int nn  = n & 1023;
                    const int h   = nn >> 6;
                    const int e   = nn & 63;
                    const int b   = r >> 12;
                    const int s   = r & (Sn - 1);
                    float* arr = (mat == 0) ? Qo : (mat == 1) ? Ko : Vo;
                    *(float2*)&arr[((size_t)(b * Hn + h) * Sn + s) * DHn + e] =
                        make_float2(v0, v1);
                }
            }
        }
    }
}

// ---------------------------------------------------------------------------
// Sparse BigBird attention (R2 design; epilogue emits ctx as bf16 hi/lo)
// ---------------------------------------------------------------------------
__global__ __launch_bounds__(256)
void attn_k(const float* __restrict__ to_mask,
            const float* __restrict__ band_mask,
            const float* __restrict__ from_mask)
{
    extern __shared__ float sm[];
    constexpr int SP = 68;
    float* qsT = sm;
    float* ksT = sm + 64 * SP;
    float* vs  = sm + 2 * 64 * SP;
    float* psT = sm + 3 * 64 * SP;

    const int idx = blockIdx.x;
    const int jb  = idx >> 5;
    const int bh  = idx & 31;
    const int b   = bh >> 4, h = bh & 15;

    const int t  = threadIdx.x;
    const int tx = t & 15, ty = t >> 4;

    const float* qg    = g_q + ((size_t)(b * Hn + h) * Sn + jb * 64) * DHn;
    const float* kbase = g_k + (size_t)(b * Hn + h) * Sn * DHn;
    const float* vbase = g_v + (size_t)(b * Hn + h) * Sn * DHn;

    for (int i = t; i < 64 * 16; i += 256) {
        const int row = i >> 4;
        const int e4  = (i & 15) << 2;
        float4 qv = *(const float4*)(qg + row * 64 + e4);
        qsT[(e4 + 0) * SP + row] = qv.x;
        qsT[(e4 + 1) * SP + row] = qv.y;
        qsT[(e4 + 2) * SP + row] = qv.z;
        qsT[(e4 + 3) * SP + row] = qv.w;
    }

    float mrow[4], lrow[4];
    unsigned long long acc[4][2];
#pragma unroll
    for (int i = 0; i < 4; i++) {
        mrow[i] = -1e30f; lrow[i] = 0.f;
        acc[i][0] = 0ull; acc[i][1] = 0ull;
    }

    const int ntiles = (jb < NGn) ? 64 : 5;
    const float rs = 0.125f;

    for (int kt = 0; kt < ntiles; ++kt) {
        int kb, mtype = 0, kc0 = 0;
        if (jb < NGn)            { kb = kt * 64; }
        else if (jb == NGn)      { kb = kt * 64; }
        else if (jb == NBn - 1)  { kb = (kt < 2) ? kt * 64 : (Sn - 192 + (kt - 2) * 64); }
        else {
            if (kt < 2)          { kb = kt * 64; }
            else { kb = (jb - 1) * 64 + (kt - 2) * 64; mtype = 1; kc0 = (kt - 2) * 64; }
        }

        __syncthreads();
        const float* kp = kbase + (size_t)kb * 64;
        const float* vp = vbase + (size_t)kb * 64;
        for (int i = t; i < 64 * 16; i += 256) {
            const int key = i >> 4;
            const int e4  = (i & 15) << 2;
            float4 kv = *(const float4*)(kp + key * 64 + e4);
            ksT[(e4 + 0) * SP + key] = kv.x;
            ksT[(e4 + 1) * SP + key] = kv.y;
            ksT[(e4 + 2) * SP + key] = kv.z;
            ksT[(e4 + 3) * SP + key] = kv.w;
            *(float4*)&vs[key * SP + e4] = *(const float4*)(vp + key * 64 + e4);
        }
        __syncthreads();

        unsigned long long s2[4][2];
#pragma unroll
        for (int i = 0; i < 4; i++) { s2[i][0] = 0ull; s2[i][1] = 0ull; }
#pragma unroll 8
        for (int e = 0; e < 64; e++) {
            float4 qf = *(const float4*)&qsT[e * SP + ty * 4];
            ulonglong2 kf = *(const ulonglong2*)&ksT[e * SP + tx * 4];
            float qa[4] = {qf.x, qf.y, qf.z, qf.w};
#pragma unroll
            for (int i = 0; i < 4; i++) {
                unsigned long long qq = bcast2(qa[i]);
                fma2(s2[i][0], qq, kf.x);
                fma2(s2[i][1], qq, kf.y);
            }
        }
        float s[4][4];
#pragma unroll
        for (int i = 0; i < 4; i++) {
            unpack2(s[i][0], s[i][1], s2[i][0]);
            unpack2(s[i][2], s[i][3], s2[i][1]);
        }

        if (mtype == 0) {
            float pen[4];
#pragma unroll
            for (int j = 0; j < 4; j++)
                pen[j] = (1.0f - to_mask[b * Sn + kb + tx * 4 + j]) * -10000.0f;
#pragma unroll
            for (int i = 0; i < 4; i++)
#pragma unroll
                for (int j = 0; j < 4; j++) s[i][j] = s[i][j] * rs + pen[j];
        } else {
            const int m_idx = jb - (NGn + 1);
            const float* bm = band_mask + ((size_t)(b * NMIDn + m_idx) * 64) * 192;
#pragma unroll
            for (int i = 0; i < 4; i++) {
                const int qi = ty * 4 + i;
#pragma unroll
                for (int j = 0; j < 4; j++) {
                    const int kc = kc0 + tx * 4 + j;
                    s[i][j] = s[i][j] * rs + (1.0f - bm[qi * 192 + kc]) * -10000.0f;
                }
            }
        }

        float tmax[4];
#pragma unroll
        for (int i = 0; i < 4; i++)
            tmax[i] = fmaxf(fmaxf(s[i][0], s[i][1]), fmaxf(s[i][2], s[i][3]));
#pragma unroll
        for (int off = 8; off >= 1; off >>= 1)
#pragma unroll
            for (int i = 0; i < 4; i++)
                tmax[i] = fmaxf(tmax[i], __shfl_xor_sync(0xffffffffu, tmax[i], off));

        float rsum[4];
#pragma unroll
        for (int i = 0; i < 4; i++) {
            const float nm   = fmaxf(mrow[i], tmax[i]);
            const float corr = __expf(mrow[i] - nm);
            mrow[i] = nm;
            lrow[i] *= corr;
            unsigned long long c2 = bcast2(corr);
            mul2(acc[i][0], c2);
            mul2(acc[i][1], c2);
            float rsi = 0.f;
#pragma unroll
            for (int j = 0; j < 4; j++) {
                const float p = __expf(s[i][j] - nm);
                s[i][j] = p;
                rsi += p;
            }
            rsum[i] = rsi;
        }
#pragma unroll
        for (int off = 8; off >= 1; off >>= 1)
#pragma unroll
            for (int i = 0; i < 4; i++)
                rsum[i] += __shfl_xor_sync(0xffffffffu, rsum[i], off);
#pragma unroll
        for (int i = 0; i < 4; i++) lrow[i] += rsum[i];

#pragma unroll
        for (int j = 0; j < 4; j++)
#pragma unroll
            for (int i = 0; i < 4; i++)
                psT[(tx * 4 + j) * SP + ty * 4 + i] = s[i][j];
        __syncthreads();

#pragma unroll 8
        for (int key = 0; key < 64; key++) {
            float4 pf = *(const float4*)&psT[key * SP + ty * 4];
            ulonglong2 vf = *(const ulonglong2*)&vs[key * SP + tx * 4];
            float pa[4] = {pf.x, pf.y, pf.z, pf.w};
#pragma unroll
            for (int i = 0; i < 4; i++) {
                unsigned long long pp = bcast2(pa[i]);
                fma2(acc[i][0], pp, vf.x);
                fma2(acc[i][1], pp, vf.y);
            }
        }
    }

    // epilogue: normalize, apply from_mask, split to bf16 hi/lo ctx
#pragma unroll
    for (int i = 0; i < 4; i++) {
        const int srow = jb * 64 + ty * 4 + i;
        const float fm = from_mask[b * Sn + srow];
        const float sc = fm / lrow[i];
        float o0, o1, o2, o3;
        unpack2(o0, o1, acc[i][0]);
        unpack2(o2, o3, acc[i][1]);
        o0 *= sc; o1 *= sc; o2 *= sc; o3 *= sc;
        __nv_bfloat16 h0, h1, h2, h3, l0, l1, l2, l3;
        bsplit(o0, h0, l0); bsplit(o1, h1, l1);
        bsplit(o2, h2, l2); bsplit(o3, h3, l3);
        const size_t oidx = (size_t)(b * Sn + srow) * Dn + h * 64 + tx * 4;
        __nv_bfloat162 p;
        p.x = h0; p.y = h1; *(__nv_bfloat162*)&g_Chi[oidx]     = p;
        p.x = h2; p.y = h3; *(__nv_bfloat162*)&g_Chi[oidx + 2] = p;
        p.x = l0; p.y = l1; *(__nv_bfloat162*)&g_Clo[oidx]     = p;
        p.x = l2; p.y = l3; *(__nv_bfloat162*)&g_Clo[oidx + 2] = p;
    }
}

// ---------------------------------------------------------------------------
extern "C" void kernel_launch(void* const* d_in, const int* in_sizes, int n_in,
                              void* d_out, int out_size)
{
    const float* tokens    = (const float*)d_in[0];
    const float* band_mask = (const float*)d_in[1];
    const float* from_mask = (const float*)d_in[2];
    const float* to_mask   = (const float*)d_in[3];
    const float* Wq        = (const float*)d_in[4];
    const float* Wk        = (const float*)d_in[5];
    const float* Wv        = (const float*)d_in[6];
    const float* Wu        = (const float*)d_in[7];
    const float* bu        = (const float*)d_in[8];
    (void)in_sizes; (void)n_in; (void)out_size;

    float *qp, *kp, *vp;
    __nv_bfloat16 *ahi, *alo, *bqh, *bql, *buh, *bul, *chi, *clo;
    cudaGetSymbolAddress((void**)&qp,  g_q);
    cudaGetSymbolAddress((void**)&kp,  g_k);
    cudaGetSymbolAddress((void**)&vp,  g_v);
    cudaGetSymbolAddress((void**)&ahi, g_Ahi);
    cudaGetSymbolAddress((void**)&alo, g_Alo);
    cudaGetSymbolAddress((void**)&bqh, g_Bqkv_hi);
    cudaGetSymbolAddress((void**)&bql, g_Bqkv_lo);
    cudaGetSymbolAddress((void**)&buh, g_Bu_hi);
    cudaGetSymbolAddress((void**)&bul, g_Bu_lo);
    cudaGetSymbolAddress((void**)&chi, g_Chi);
    cudaGetSymbolAddress((void**)&clo, g_Clo);

    cudaFuncSetAttribute(attn_k, cudaFuncAttributeMaxDynamicSharedMemorySize, ATTN_SMEM);
    cudaFuncSetAttribute(hmma_gemm<0>, cudaFuncAttributeMaxDynamicSharedMemorySize, GEMM_SMEM);
    cudaFuncSetAttribute(hmma_gemm<1>, cudaFuncAttributeMaxDynamicSharedMemorySize, GEMM_SMEM);

    // prep: split tokens, pack weights (transpose + split)
    split_k<<<2048, 256>>>(tokens, ahi, alo, Mrows * Dn / 4);
    dim3 pw(32, 32);
    packW_k<<<pw, dim3(32, 8)>>>(Wq, bqh, bql, 0);
    packW_k<<<pw, dim3(32, 8)>>>(Wk, bqh, bql, 1024);
    packW_k<<<pw, dim3(32, 8)>>>(Wv, bqh, bql, 2048);
    packW_k<<<pw, dim3(32, 8)>>>(Wu, buh, bul, 0);

    // fused QKV GEMM: [8192 x 3072] -> q/k/v head layout
    hmma_gemm<1><<<dim3(24, 64), 256, GEMM_SMEM>>>(ahi, alo, bqh, bql,
                                                   nullptr, nullptr, qp, kp, vp);
    // attention -> ctx (bf16 hi/lo)
    attn_k<<<Bn * Hn * NBn, 256, ATTN_SMEM>>>(to_mask, band_mask, from_mask);
    // output projection: [8192 x 1024] + bias
    hmma_gemm<0><<<dim3(8, 64), 256, GEMM_SMEM>>>(chi, clo, buh, bul,
                                                  bu, (float*)d_out,
                                                  nullptr, nullptr, nullptr);
}

// round 6
// speedup vs baseline: 2.3145x; 1.3825x over previous
#include <cuda_runtime.h>
#include <cuda_bf16.h>
#include <cstdint>

// ---------------------------------------------------------------------------
// BigBird transformer block on sm_103 (non-'a' target: no tcgen05/TMEM).
// All heavy math on the tensor pipe via warp-level mma.sync bf16 with hi/lo
// split (D = Ah.Bh + Al.Bh + Ah.Bl, error ~2^-16):
//   - fused QKV GEMM [8192 x 3072] -> q/k/v emitted as bf16 hi/lo head layout
//   - flash attention: S = Q.K^T (HMMA), online softmax on fragments,
//     PV (HMMA, ldmatrix.trans for V), ctx emitted bf16 hi/lo
//   - output GEMM: d_out = ctx @ Wu + bu
// R6 fix: attention Q/KV cp.async loops now cover all 8 16B chunks per
// 128-byte row (R5 only filled 4 -> garbage in e=32..63 -> NaN).
// ---------------------------------------------------------------------------

namespace {
constexpr int Bn    = 2;
constexpr int Sn    = 4096;
constexpr int Dn    = 1024;
constexpr int Hn    = 16;
constexpr int DHn   = 64;
constexpr int NBn   = 64;
constexpr int NGn   = 2;
constexpr int NMIDn = 60;
constexpr int Mrows = Bn * Sn;              // 8192

// GEMM tiling
constexpr int BK      = 32;
constexpr int NCHUNK  = Dn / BK;             // 32
constexpr int ROWB    = 80;                  // padded row bytes (32 bf16)
constexpr int MATB    = 128 * ROWB;
constexpr int STG     = 4 * MATB;            // 40960 B / stage
constexpr int GEMM_SMEM = 3 * STG;           // 122880 B

// attention smem: rows of 64 bf16 padded to 144 B
constexpr int AROW    = 144;
constexpr int AMAT    = 64 * AROW;           // 9216 B per 64x64 bf16 matrix
constexpr int ASTAGE  = 4 * AMAT;            // Kh,Kl,Vh,Vl = 36864 B
constexpr int AQ_BYTES = 2 * AMAT;           // Qh,Ql
constexpr int ATTN_SMEM = AQ_BYTES + 2 * ASTAGE;  // 92160 B
}

// ---- scratch (device globals) ----------------------------------------------
__device__ __nv_bfloat16 g_qhi[Bn * Hn * Sn * DHn], g_qlo[Bn * Hn * Sn * DHn];
__device__ __nv_bfloat16 g_khi[Bn * Hn * Sn * DHn], g_klo[Bn * Hn * Sn * DHn];
__device__ __nv_bfloat16 g_vhi[Bn * Hn * Sn * DHn], g_vlo[Bn * Hn * Sn * DHn];
__device__ __nv_bfloat16 g_Ahi[Mrows * Dn],      g_Alo[Mrows * Dn];
__device__ __nv_bfloat16 g_Bqkv_hi[3 * Dn * Dn], g_Bqkv_lo[3 * Dn * Dn];
__device__ __nv_bfloat16 g_Bu_hi[Dn * Dn],       g_Bu_lo[Dn * Dn];
__device__ __nv_bfloat16 g_Chi[Mrows * Dn],      g_Clo[Mrows * Dn];

// ---------------------------------------------------------------------------
// PTX helpers
// ---------------------------------------------------------------------------
__device__ __forceinline__ uint32_t smem_u32(const void* p) {
    uint32_t a;
    asm("{ .reg .u64 t; cvta.to.shared.u64 t, %1; cvt.u32.u64 %0, t; }" : "=r"(a) : "l"(p));
    return a;
}
__device__ __forceinline__ void cpa16(uint32_t dst, const void* src) {
    asm volatile("cp.async.cg.shared.global [%0], [%1], 16;" :: "r"(dst), "l"(src));
}
__device__ __forceinline__ void cpa_commit() {
    asm volatile("cp.async.commit_group;" ::: "memory");
}
template <int N>
__device__ __forceinline__ void cpa_wait() {
    asm volatile("cp.async.wait_group %0;" :: "n"(N) : "memory");
}
__device__ __forceinline__ void ldm4(uint32_t* r, uint32_t addr) {
    asm volatile("ldmatrix.sync.aligned.m8n8.x4.shared.b16 {%0,%1,%2,%3}, [%4];"
                 : "=r"(r[0]), "=r"(r[1]), "=r"(r[2]), "=r"(r[3]) : "r"(addr));
}
__device__ __forceinline__ void ldm4t(uint32_t* r, uint32_t addr) {
    asm volatile("ldmatrix.sync.aligned.m8n8.x4.trans.shared.b16 {%0,%1,%2,%3}, [%4];"
                 : "=r"(r[0]), "=r"(r[1]), "=r"(r[2]), "=r"(r[3]) : "r"(addr));
}
__device__ __forceinline__ void mma16816(float* c, const uint32_t* a,
                                         uint32_t b0, uint32_t b1) {
    asm volatile(
        "mma.sync.aligned.m16n8k16.row.col.f32.bf16.bf16.f32 "
        "{%0,%1,%2,%3}, {%4,%5,%6,%7}, {%8,%9}, {%0,%1,%2,%3};"
        : "+f"(c[0]), "+f"(c[1]), "+f"(c[2]), "+f"(c[3])
        : "r"(a[0]), "r"(a[1]), "r"(a[2]), "r"(a[3]), "r"(b0), "r"(b1));
}
__device__ __forceinline__ uint32_t packbf(float lo, float hi) {
    uint32_t r;
    asm("cvt.rn.bf16x2.f32 %0, %1, %2;" : "=r"(r) : "f"(hi), "f"(lo));
    return r;
}
__device__ __forceinline__ void bsplit(float v, __nv_bfloat16& h, __nv_bfloat16& l) {
    h = __float2bfloat16(v);
    l = __float2bfloat16(v - __bfloat162float(h));
}
__device__ __forceinline__ void bsplit_pack(float v0, float v1,
                                            uint32_t& hp, uint32_t& lp) {
    const uint32_t u0 = __float_as_uint(v0), u1 = __float_as_uint(v1);
    hp = __byte_perm(u0, u1, 0x7632);
    const float l0 = v0 - __uint_as_float(u0 & 0xFFFF0000u);
    const float l1 = v1 - __uint_as_float(u1 & 0xFFFF0000u);
    lp = packbf(l0, l1);
}

// ---------------------------------------------------------------------------
// prep kernels
// ---------------------------------------------------------------------------
__global__ void split_k(const float* __restrict__ X,
                        __nv_bfloat16* __restrict__ Hi,
                        __nv_bfloat16* __restrict__ Lo, int n4)
{
    for (int i = blockIdx.x * blockDim.x + threadIdx.x; i < n4;
         i += gridDim.x * blockDim.x) {
        float4 v = ((const float4*)X)[i];
        __nv_bfloat16 h0, h1, h2, h3, l0, l1, l2, l3;
        bsplit(v.x, h0, l0); bsplit(v.y, h1, l1);
        bsplit(v.z, h2, l2); bsplit(v.w, h3, l3);
        __nv_bfloat162 a, b;
        a.x = h0; a.y = h1; b.x = h2; b.y = h3;
        *(__nv_bfloat162*)(Hi + 4 * i)     = a;
        *(__nv_bfloat162*)(Hi + 4 * i + 2) = b;
        a.x = l0; a.y = l1; b.x = l2; b.y = l3;
        *(__nv_bfloat162*)(Lo + 4 * i)     = a;
        *(__nv_bfloat162*)(Lo + 4 * i + 2) = b;
    }
}

__global__ void packW_k(const float* __restrict__ W,
                        __nv_bfloat16* __restrict__ Bhi,
                        __nv_bfloat16* __restrict__ Blo, int nOff)
{
    __shared__ float tile[32][33];
    const int tx = threadIdx.x, ty = threadIdx.y;
    const int n0 = blockIdx.x * 32, k0 = blockIdx.y * 32;
#pragma unroll
    for (int j = 0; j < 4; j++)
        tile[ty + j * 8][tx] = W[(size_t)(k0 + ty + j * 8) * Dn + n0 + tx];
    __syncthreads();
    const int kk = k0 + tx;
#pragma unroll
    for (int j = 0; j < 4; j++) {
        const int n = n0 + ty + j * 8;
        __nv_bfloat16 h, l;
        bsplit(tile[tx][ty + j * 8], h, l);
        Bhi[(size_t)(nOff + n) * Dn + kk] = h;
        Blo[(size_t)(nOff + n) * Dn + kk] = l;
    }
}

// ---------------------------------------------------------------------------
// HMMA GEMM. MODE 1: scatter q/k/v as bf16 hi/lo head layout.
// MODE 0: d_out = D + bias.
// ---------------------------------------------------------------------------
template <int MODE>
__global__ void __launch_bounds__(256)
hmma_gemm(const __nv_bfloat16* __restrict__ Ahi, const __nv_bfloat16* __restrict__ Alo,
          const __nv_bfloat16* __restrict__ Bhi, const __nv_bfloat16* __restrict__ Blo,
          const float* __restrict__ bias, float* __restrict__ Cout)
{
    extern __shared__ char smem[];
    const uint32_t sb = smem_u32(smem);
    const int t    = threadIdx.x;
    const int lane = t & 31;
    const int wid  = t >> 5;
    const int wm   = (wid & 1) << 6;
    const int wn   = (wid >> 1) << 5;
    const int m0   = blockIdx.y << 7;
    const int n0   = blockIdx.x << 7;

    auto load_stage = [&](int kc, int s) {
        const int kel = kc * BK;
        const uint32_t stb = sb + s * STG;
#pragma unroll
        for (int j = 0; j < 8; j++) {
            const int idx = t + (j << 8);
            const int mat = idx >> 9;
            const int rr  = (idx >> 2) & 127;
            const int cc  = idx & 3;
            const __nv_bfloat16* src;
            if (mat < 2)
                src = (mat ? Alo : Ahi) + (size_t)(m0 + rr) * Dn + kel + (cc << 3);
            else
                src = (mat == 2 ? Bhi : Blo) + (size_t)(n0 + rr) * Dn + kel + (cc << 3);
            cpa16(stb + mat * MATB + rr * ROWB + (cc << 4), src);
        }
        cpa_commit();
    };

    float acc[4][4][4];
#pragma unroll
    for (int i = 0; i < 4; i++)
#pragma unroll
        for (int j = 0; j < 4; j++)
#pragma unroll
            for (int q = 0; q < 4; q++) acc[i][j][q] = 0.f;

    load_stage(0, 0);
    load_stage(1, 1);

    for (int kc = 0; kc < NCHUNK; ++kc) {
        cpa_wait<1>();
        __syncthreads();
        const uint32_t stb = sb + (kc % 3) * STG;

#pragma unroll
        for (int k16 = 0; k16 < 2; k16++) {
            uint32_t ah[16], al[16];
            const uint32_t abase = stb + (wm + (lane & 15)) * ROWB +
                                   (k16 << 5) + ((lane >> 4) << 4);
#pragma unroll
            for (int mt = 0; mt < 4; mt++) {
                ldm4(ah + 4 * mt, abase + mt * 16 * ROWB);
                ldm4(al + 4 * mt, abase + mt * 16 * ROWB + MATB);
            }
#pragma unroll
            for (int ng = 0; ng < 2; ng++) {
                uint32_t bh[4], bl[4];
                const uint32_t bbase = stb + 2 * MATB +
                                       (wn + ng * 16 + (lane & 15)) * ROWB +
                                       (k16 << 5) + ((lane >> 4) << 4);
                ldm4(bh, bbase);
                ldm4(bl, bbase + MATB);
#pragma unroll
                for (int mt = 0; mt < 4; mt++) {
#pragma unroll
                    for (int nn = 0; nn < 2; nn++) {
                        float* c = acc[mt][ng * 2 + nn];
                        const uint32_t b0  = nn ? bh[1] : bh[0];
                        const uint32_t b1  = nn ? bh[3] : bh[2];
                        const uint32_t lb0 = nn ? bl[1] : bl[0];
                        const uint32_t lb1 = nn ? bl[3] : bl[2];
                        mma16816(c, ah + 4 * mt, b0, b1);
                        mma16816(c, al + 4 * mt, b0, b1);
                        mma16816(c, ah + 4 * mt, lb0, lb1);
                    }
                }
            }
        }
        if (kc + 2 < NCHUNK) load_stage(kc + 2, (kc + 2) % 3);
    }

    const int rbase = m0 + wm + (lane >> 2);
    const int cbase = (lane & 3) << 1;
#pragma unroll
    for (int mt = 0; mt < 4; mt++) {
#pragma unroll
        for (int nf = 0; nf < 4; nf++) {
            const int n = n0 + wn + ((nf >> 1) << 4) + ((nf & 1) << 3) + cbase;
            const float* c = acc[mt][nf];
#pragma unroll
            for (int half = 0; half < 2; half++) {
                const int r = rbase + mt * 16 + half * 8;
                const float v0 = c[2 * half], v1 = c[2 * half + 1];
                if (MODE == 0) {
                    *(float2*)&Cout[(size_t)r * Dn + n] =
                        make_float2(v0 + bias[n], v1 + bias[n + 1]);
                } else {
                    const int mat = n >> 10;
                    const int nn  = n & 1023;
                    const int h   = nn >> 6;
                    const int e   = nn & 63;
                    const int b   = r >> 12;
                    const int s   = r & (Sn - 1);
                    __nv_bfloat16* hi_arr =
                        (mat == 0) ? g_qhi : (mat == 1) ? g_khi : g_vhi;
                    __nv_bfloat16* lo_arr =
                        (mat == 0) ? g_qlo : (mat == 1) ? g_klo : g_vlo;
                    __nv_bfloat16 h0, h1, l0, l1;
                    bsplit(v0, h0, l0);
                    bsplit(v1, h1, l1);
                    const size_t off = ((size_t)(b * Hn + h) * Sn + s) * DHn + e;
                    __nv_bfloat162 p;
                    p.x = h0; p.y = h1; *(__nv_bfloat162*)&hi_arr[off] = p;
                    p.x = l0; p.y = l1; *(__nv_bfloat162*)&lo_arr[off] = p;
                }
            }
        }
    }
}

// ---------------------------------------------------------------------------
// Flash attention, warp-MMA. One CTA per (jb, b, h): 2048 CTAs, 4 warps.
// ---------------------------------------------------------------------------
__device__ __forceinline__ int kb_of(int jb, int kt, int& mtype, int& kc0) {
    mtype = 0; kc0 = 0;
    if (jb <= NGn) return kt * 64;
    if (jb == NBn - 1) return (kt < 2) ? kt * 64 : (Sn - 192 + (kt - 2) * 64);
    if (kt < 2) return kt * 64;
    mtype = 1; kc0 = (kt - 2) * 64;
    return (jb - 1) * 64 + (kt - 2) * 64;
}

__global__ void __launch_bounds__(128, 2)
attn_k(const float* __restrict__ to_mask,
       const float* __restrict__ band_mask,
       const float* __restrict__ from_mask)
{
    extern __shared__ char smem[];
    const uint32_t sb = smem_u32(smem);
    const int t = threadIdx.x, lane = t & 31, wid = t >> 5;
    const int idx = blockIdx.x;
    const int jb  = idx >> 5;             // global blocks first
    const int bh  = idx & 31;
    const int b   = bh >> 4, h = bh & 15;
    const int wm  = wid << 4;             // warp row offset

    const size_t hoff = (size_t)(b * Hn + h) * Sn * DHn;
    const __nv_bfloat16* qhg = g_qhi + hoff + (size_t)jb * 64 * DHn;
    const __nv_bfloat16* qlg = g_qlo + hoff + (size_t)jb * 64 * DHn;
    const __nv_bfloat16* khg = g_khi + hoff;
    const __nv_bfloat16* klg = g_klo + hoff;
    const __nv_bfloat16* vhg = g_vhi + hoff;
    const __nv_bfloat16* vlg = g_vlo + hoff;

    // Q tiles -> smem (hi at 0, lo at AMAT): 2 mats x 64 rows x 8 chunks
#pragma unroll
    for (int j = 0; j < 8; j++) {
        const int i2 = t + (j << 7);
        const int mat = i2 >> 9;
        const int rr  = (i2 >> 3) & 63;
        const int cc  = i2 & 7;
        cpa16(sb + mat * AMAT + rr * AROW + (cc << 4),
              (mat ? qlg : qhg) + rr * DHn + (cc << 3));
    }
    cpa_commit();

    auto loadKV = [&](int kb, int s) {
        const uint32_t base = sb + AQ_BYTES + s * ASTAGE;
        // 4 mats x 64 rows x 8 chunks = 2048
#pragma unroll
        for (int j = 0; j < 16; j++) {
            const int i2 = t + (j << 7);
            const int mat = i2 >> 9;
            const int rr  = (i2 >> 3) & 63;
            const int cc  = i2 & 7;
            const __nv_bfloat16* src =
                (mat == 0 ? khg : mat == 1 ? klg : mat == 2 ? vhg : vlg) +
                (size_t)(kb + rr) * DHn + (cc << 3);
            cpa16(base + mat * AMAT + rr * AROW + (cc << 4), src);
        }
        cpa_commit();
    };

    const int ntiles = (jb < NGn) ? 64 : 5;
    int mty, kc0_;
    loadKV(kb_of(jb, 0, mty, kc0_), 0);

    uint32_t qh[4][4], ql[4][4];
    float pv[8][4];
#pragma unroll
    for (int f = 0; f < 8; f++)
#pragma unroll
        for (int q = 0; q < 4; q++) pv[f][q] = 0.f;
    float mrow0 = -1e30f, mrow1 = -1e30f, lrow0 = 0.f, lrow1 = 0.f;

    const float rs = 0.125f;

    for (int kt = 0; kt < ntiles; ++kt) {
        if (kt + 1 < ntiles) {
            int mt2, kc2;
            loadKV(kb_of(jb, kt + 1, mt2, kc2), (kt + 1) & 1);
            cpa_wait<1>();
        } else {
            cpa_wait<0>();
        }
        __syncthreads();

        if (kt == 0) {  // Q fragments (once)
            const uint32_t qbase = sb + (wm + (lane & 15)) * AROW + ((lane >> 4) << 4);
#pragma unroll
            for (int ks = 0; ks < 4; ks++) {
                ldm4(qh[ks], qbase + (ks << 5));
                ldm4(ql[ks], qbase + (ks << 5) + AMAT);
            }
        }

        int mtype, kcol0;
        const int kb = kb_of(jb, kt, mtype, kcol0);
        const uint32_t SK = sb + AQ_BYTES + (kt & 1) * ASTAGE;
        const uint32_t SV = SK + 2 * AMAT;

        // ---- S = Q.K^T (hi/lo 3 products) ---------------------------------
        float sf[8][4];
#pragma unroll
        for (int f = 0; f < 8; f++)
#pragma unroll
            for (int q = 0; q < 4; q++) sf[f][q] = 0.f;
#pragma unroll
        for (int ks = 0; ks < 4; ks++) {
#pragma unroll
            for (int kg = 0; kg < 4; kg++) {
                uint32_t kh4[4], kl4[4];
                const uint32_t ka = SK + (kg * 16 + (lane & 15)) * AROW +
                                    (ks << 5) + ((lane >> 4) << 4);
                ldm4(kh4, ka);
                ldm4(kl4, ka + AMAT);
#pragma unroll
                for (int nn = 0; nn < 2; nn++) {
                    float* c = sf[kg * 2 + nn];
                    const uint32_t b0  = nn ? kh4[1] : kh4[0];
                    const uint32_t b1  = nn ? kh4[3] : kh4[2];
                    const uint32_t lb0 = nn ? kl4[1] : kl4[0];
                    const uint32_t lb1 = nn ? kl4[3] : kl4[2];
                    mma16816(c, qh[ks], b0, b1);
                    mma16816(c, ql[ks], b0, b1);
                    mma16816(c, qh[ks], lb0, lb1);
                }
            }
        }

        // ---- scale + mask --------------------------------------------------
        const int colb = (lane & 3) << 1;
        if (mtype == 0) {
#pragma unroll
            for (int f = 0; f < 8; f++) {
                const int key = kb + f * 8 + colb;
                const float p0 = (1.0f - to_mask[b * Sn + key]) * -10000.0f;
                const float p1 = (1.0f - to_mask[b * Sn + key + 1]) * -10000.0f;
                sf[f][0] = sf[f][0] * rs + p0;
                sf[f][1] = sf[f][1] * rs + p1;
                sf[f][2] = sf[f][2] * rs + p0;
                sf[f][3] = sf[f][3] * rs + p1;
            }
        } else {
            const int m_idx = jb - (NGn + 1);
            const int qi0 = wm + (lane >> 2);
            const float* bm0 = band_mask +
                ((size_t)(b * NMIDn + m_idx) * 64 + qi0) * 192 + kcol0 + colb;
#pragma unroll
            for (int f = 0; f < 8; f++) {
                sf[f][0] = sf[f][0] * rs + (1.0f - bm0[f * 8]) * -10000.0f;
                sf[f][1] = sf[f][1] * rs + (1.0f - bm0[f * 8 + 1]) * -10000.0f;
                sf[f][2] = sf[f][2] * rs + (1.0f - bm0[8 * 192 + f * 8]) * -10000.0f;
                sf[f][3] = sf[f][3] * rs + (1.0f - bm0[8 * 192 + f * 8 + 1]) * -10000.0f;
            }
        }

        // ---- online softmax ------------------------------------------------
        float mx0 = -1e30f, mx1 = -1e30f;
#pragma unroll
        for (int f = 0; f < 8; f++) {
            mx0 = fmaxf(mx0, fmaxf(sf[f][0], sf[f][1]));
            mx1 = fmaxf(mx1, fmaxf(sf[f][2], sf[f][3]));
        }
        mx0 = fmaxf(mx0, __shfl_xor_sync(0xffffffffu, mx0, 1));
        mx0 = fmaxf(mx0, __shfl_xor_sync(0xffffffffu, mx0, 2));
        mx1 = fmaxf(mx1, __shfl_xor_sync(0xffffffffu, mx1, 1));
        mx1 = fmaxf(mx1, __shfl_xor_sync(0xffffffffu, mx1, 2));

        const float nm0 = fmaxf(mrow0, mx0), nm1 = fmaxf(mrow1, mx1);
        const float corr0 = __expf(mrow0 - nm0), corr1 = __expf(mrow1 - nm1);
        mrow0 = nm0; mrow1 = nm1;
        lrow0 *= corr0; lrow1 *= corr1;
#pragma unroll
        for (int f = 0; f < 8; f++) {
            pv[f][0] *= corr0; pv[f][1] *= corr0;
            pv[f][2] *= corr1; pv[f][3] *= corr1;
        }

        float rs0 = 0.f, rs1 = 0.f;
#pragma unroll
        for (int f = 0; f < 8; f++) {
            sf[f][0] = __expf(sf[f][0] - nm0);
            sf[f][1] = __expf(sf[f][1] - nm0);
            sf[f][2] = __expf(sf[f][2] - nm1);
            sf[f][3] = __expf(sf[f][3] - nm1);
            rs0 += sf[f][0] + sf[f][1];
            rs1 += sf[f][2] + sf[f][3];
        }
        rs0 += __shfl_xor_sync(0xffffffffu, rs0, 1);
        rs0 += __shfl_xor_sync(0xffffffffu, rs0, 2);
        rs1 += __shfl_xor_sync(0xffffffffu, rs1, 1);
        rs1 += __shfl_xor_sync(0xffffffffu, rs1, 2);
        lrow0 += rs0; lrow1 += rs1;

        // ---- PV: P (hi/lo in-register) @ V (hi/lo via ldmatrix.trans) ------
#pragma unroll
        for (int kg = 0; kg < 4; kg++) {
            uint32_t pa[4], pl[4];
            bsplit_pack(sf[2 * kg][0],     sf[2 * kg][1],     pa[0], pl[0]);
            bsplit_pack(sf[2 * kg][2],     sf[2 * kg][3],     pa[1], pl[1]);
            bsplit_pack(sf[2 * kg + 1][0], sf[2 * kg + 1][1], pa[2], pl[2]);
            bsplit_pack(sf[2 * kg + 1][2], sf[2 * kg + 1][3], pa[3], pl[3]);
#pragma unroll
            for (int eg = 0; eg < 4; eg++) {
                uint32_t vh4[4], vl4[4];
                const uint32_t va = SV +
                    (kg * 16 + (((lane >> 3) & 1) << 3) + (lane & 7)) * AROW +
                    (eg << 5) + ((lane >> 4) << 4);
                ldm4t(vh4, va);
                ldm4t(vl4, va + AMAT);
#pragma unroll
                for (int nn = 0; nn < 2; nn++) {
                    float* c = pv[eg * 2 + nn];
                    const uint32_t b0  = vh4[nn * 2];
                    const uint32_t b1  = vh4[nn * 2 + 1];
                    const uint32_t lb0 = vl4[nn * 2];
                    const uint32_t lb1 = vl4[nn * 2 + 1];
                    mma16816(c, pa, b0, b1);
                    mma16816(c, pl, b0, b1);
                    mma16816(c, pa, lb0, lb1);
                }
            }
        }
        __syncthreads();   // done reading this stage before it is reloaded
    }

    // ---- epilogue ----------------------------------------------------------
    const int srow0 = jb * 64 + wm + (lane >> 2);
    const int srow1 = srow0 + 8;
    const float sc0 = from_mask[b * Sn + srow0] / lrow0;
    const float sc1 = from_mask[b * Sn + srow1] / lrow1;
#pragma unroll
    for (int f = 0; f < 8; f++) {
        const int e = f * 8 + ((lane & 3) << 1);
        const size_t o0 = (size_t)(b * Sn + srow0) * Dn + h * 64 + e;
        const size_t o1 = (size_t)(b * Sn + srow1) * Dn + h * 64 + e;
        __nv_bfloat16 h0, h1, l0, l1;
        bsplit(pv[f][0] * sc0, h0, l0);
        bsplit(pv[f][1] * sc0, h1, l1);
        __nv_bfloat162 p;
        p.x = h0; p.y = h1; *(__nv_bfloat162*)&g_Chi[o0] = p;
        p.x = l0; p.y = l1; *(__nv_bfloat162*)&g_Clo[o0] = p;
        bsplit(pv[f][2] * sc1, h0, l0);
        bsplit(pv[f][3] * sc1, h1, l1);
        p.x = h0; p.y = h1; *(__nv_bfloat162*)&g_Chi[o1] = p;
        p.x = l0; p.y = l1; *(__nv_bfloat162*)&g_Clo[o1] = p;
    }
}

// ---------------------------------------------------------------------------
extern "C" void kernel_launch(void* const* d_in, const int* in_sizes, int n_in,
                              void* d_out, int out_size)
{
    const float* tokens    = (const float*)d_in[0];
    const float* band_mask = (const float*)d_in[1];
    const float* from_mask = (const float*)d_in[2];
    const float* to_mask   = (const float*)d_in[3];
    const float* Wq        = (const float*)d_in[4];
    const float* Wk        = (const float*)d_in[5];
    const float* Wv        = (const float*)d_in[6];
    const float* Wu        = (const float*)d_in[7];
    const float* bu        = (const float*)d_in[8];
    (void)in_sizes; (void)n_in; (void)out_size;

    __nv_bfloat16 *ahi, *alo, *bqh, *bql, *buh, *bul, *chi, *clo;
    cudaGetSymbolAddress((void**)&ahi, g_Ahi);
    cudaGetSymbolAddress((void**)&alo, g_Alo);
    cudaGetSymbolAddress((void**)&bqh, g_Bqkv_hi);
    cudaGetSymbolAddress((void**)&bql, g_Bqkv_lo);
    cudaGetSymbolAddress((void**)&buh, g_Bu_hi);
    cudaGetSymbolAddress((void**)&bul, g_Bu_lo);
    cudaGetSymbolAddress((void**)&chi, g_Chi);
    cudaGetSymbolAddress((void**)&clo, g_Clo);

    cudaFuncSetAttribute(attn_k, cudaFuncAttributeMaxDynamicSharedMemorySize, ATTN_SMEM);
    cudaFuncSetAttribute(hmma_gemm<0>, cudaFuncAttributeMaxDynamicSharedMemorySize, GEMM_SMEM);
    cudaFuncSetAttribute(hmma_gemm<1>, cudaFuncAttributeMaxDynamicSharedMemorySize, GEMM_SMEM);

    split_k<<<2048, 256>>>(tokens, ahi, alo, Mrows * Dn / 4);
    dim3 pw(32, 32);
    packW_k<<<pw, dim3(32, 8)>>>(Wq, bqh, bql, 0);
    packW_k<<<pw, dim3(32, 8)>>>(Wk, bqh, bql, 1024);
    packW_k<<<pw, dim3(32, 8)>>>(Wv, bqh, bql, 2048);
    packW_k<<<pw, dim3(32, 8)>>>(Wu, buh, bul, 0);

    hmma_gemm<1><<<dim3(24, 64), 256, GEMM_SMEM>>>(ahi, alo, bqh, bql,
                                                   nullptr, nullptr);
    attn_k<<<Bn * Hn * NBn, 128, ATTN_SMEM>>>(to_mask, band_mask, from_mask);
    hmma_gemm<0><<<dim3(8, 64), 256, GEMM_SMEM>>>(chi, clo, buh, bul,
                                                  bu, (float*)d_out);
}

// round 7
// speedup vs baseline: 2.5113x; 1.0850x over previous
#include <cuda_runtime.h>
#include <cuda_bf16.h>
#include <cstdint>

// ---------------------------------------------------------------------------
// BigBird transformer block on sm_103 (non-'a' target: no tcgen05/TMEM).
// All heavy math on the tensor pipe via warp-level mma.sync bf16 with hi/lo
// split (D = Ah.Bh + Al.Bh + Ah.Bl, error ~2^-16).
// R7: GEMM 2-stage pipeline (81.9KB smem) + launch_bounds(256,2) -> 2 CTA/SM;
//     packW fused into one launch.
// ---------------------------------------------------------------------------

namespace {
constexpr int Bn    = 2;
constexpr int Sn    = 4096;
constexpr int Dn    = 1024;
constexpr int Hn    = 16;
constexpr int DHn   = 64;
constexpr int NBn   = 64;
constexpr int NGn   = 2;
constexpr int NMIDn = 60;
constexpr int Mrows = Bn * Sn;              // 8192

// GEMM tiling
constexpr int BK      = 32;
constexpr int NCHUNK  = Dn / BK;             // 32
constexpr int ROWB    = 80;                  // padded row bytes (32 bf16)
constexpr int MATB    = 128 * ROWB;
constexpr int STG     = 4 * MATB;            // 40960 B / stage
constexpr int GEMM_SMEM = 2 * STG;           // 81920 B -> 2 CTAs/SM

// attention smem
constexpr int AROW    = 144;
constexpr int AMAT    = 64 * AROW;           // 9216 B
constexpr int ASTAGE  = 4 * AMAT;            // 36864 B
constexpr int AQ_BYTES = 2 * AMAT;
constexpr int ATTN_SMEM = AQ_BYTES + 2 * ASTAGE;  // 92160 B
}

// ---- scratch (device globals) ----------------------------------------------
__device__ __nv_bfloat16 g_qhi[Bn * Hn * Sn * DHn], g_qlo[Bn * Hn * Sn * DHn];
__device__ __nv_bfloat16 g_khi[Bn * Hn * Sn * DHn], g_klo[Bn * Hn * Sn * DHn];
__device__ __nv_bfloat16 g_vhi[Bn * Hn * Sn * DHn], g_vlo[Bn * Hn * Sn * DHn];
__device__ __nv_bfloat16 g_Ahi[Mrows * Dn],      g_Alo[Mrows * Dn];
__device__ __nv_bfloat16 g_Bqkv_hi[3 * Dn * Dn], g_Bqkv_lo[3 * Dn * Dn];
__device__ __nv_bfloat16 g_Bu_hi[Dn * Dn],       g_Bu_lo[Dn * Dn];
__device__ __nv_bfloat16 g_Chi[Mrows * Dn],      g_Clo[Mrows * Dn];

// ---------------------------------------------------------------------------
// PTX helpers
// ---------------------------------------------------------------------------
__device__ __forceinline__ uint32_t smem_u32(const void* p) {
    uint32_t a;
    asm("{ .reg .u64 t; cvta.to.shared.u64 t, %1; cvt.u32.u64 %0, t; }" : "=r"(a) : "l"(p));
    return a;
}
__device__ __forceinline__ void cpa16(uint32_t dst, const void* src) {
    asm volatile("cp.async.cg.shared.global [%0], [%1], 16;" :: "r"(dst), "l"(src));
}
__device__ __forceinline__ void cpa_commit() {
    asm volatile("cp.async.commit_group;" ::: "memory");
}
template <int N>
__device__ __forceinline__ void cpa_wait() {
    asm volatile("cp.async.wait_group %0;" :: "n"(N) : "memory");
}
__device__ __forceinline__ void ldm4(uint32_t* r, uint32_t addr) {
    asm volatile("ldmatrix.sync.aligned.m8n8.x4.shared.b16 {%0,%1,%2,%3}, [%4];"
                 : "=r"(r[0]), "=r"(r[1]), "=r"(r[2]), "=r"(r[3]) : "r"(addr));
}
__device__ __forceinline__ void ldm4t(uint32_t* r, uint32_t addr) {
    asm volatile("ldmatrix.sync.aligned.m8n8.x4.trans.shared.b16 {%0,%1,%2,%3}, [%4];"
                 : "=r"(r[0]), "=r"(r[1]), "=r"(r[2]), "=r"(r[3]) : "r"(addr));
}
__device__ __forceinline__ void mma16816(float* c, const uint32_t* a,
                                         uint32_t b0, uint32_t b1) {
    asm volatile(
        "mma.sync.aligned.m16n8k16.row.col.f32.bf16.bf16.f32 "
        "{%0,%1,%2,%3}, {%4,%5,%6,%7}, {%8,%9}, {%0,%1,%2,%3};"
        : "+f"(c[0]), "+f"(c[1]), "+f"(c[2]), "+f"(c[3])
        : "r"(a[0]), "r"(a[1]), "r"(a[2]), "r"(a[3]), "r"(b0), "r"(b1));
}
__device__ __forceinline__ uint32_t packbf(float lo, float hi) {
    uint32_t r;
    asm("cvt.rn.bf16x2.f32 %0, %1, %2;" : "=r"(r) : "f"(hi), "f"(lo));
    return r;
}
__device__ __forceinline__ void bsplit(float v, __nv_bfloat16& h, __nv_bfloat16& l) {
    h = __float2bfloat16(v);
    l = __float2bfloat16(v - __bfloat162float(h));
}
__device__ __forceinline__ void bsplit_pack(float v0, float v1,
                                            uint32_t& hp, uint32_t& lp) {
    const uint32_t u0 = __float_as_uint(v0), u1 = __float_as_uint(v1);
    hp = __byte_perm(u0, u1, 0x7632);
    const float l0 = v0 - __uint_as_float(u0 & 0xFFFF0000u);
    const float l1 = v1 - __uint_as_float(u1 & 0xFFFF0000u);
    lp = packbf(l0, l1);
}

// ---------------------------------------------------------------------------
// prep kernels
// ---------------------------------------------------------------------------
__global__ void split_k(const float* __restrict__ X,
                        __nv_bfloat16* __restrict__ Hi,
                        __nv_bfloat16* __restrict__ Lo, int n4)
{
    for (int i = blockIdx.x * blockDim.x + threadIdx.x; i < n4;
         i += gridDim.x * blockDim.x) {
        float4 v = ((const float4*)X)[i];
        __nv_bfloat16 h0, h1, h2, h3, l0, l1, l2, l3;
        bsplit(v.x, h0, l0); bsplit(v.y, h1, l1);
        bsplit(v.z, h2, l2); bsplit(v.w, h3, l3);
        __nv_bfloat162 a, b;
        a.x = h0; a.y = h1; b.x = h2; b.y = h3;
        *(__nv_bfloat162*)(Hi + 4 * i)     = a;
        *(__nv_bfloat162*)(Hi + 4 * i + 2) = b;
        a.x = l0; a.y = l1; b.x = l2; b.y = l3;
        *(__nv_bfloat162*)(Lo + 4 * i)     = a;
        *(__nv_bfloat162*)(Lo + 4 * i + 2) = b;
    }
}

// all four weight packs in one launch: z = 0..2 -> Wq/Wk/Wv into Bqkv, 3 -> Wu
__global__ void packW_all(const float* __restrict__ Wq, const float* __restrict__ Wk,
                          const float* __restrict__ Wv, const float* __restrict__ Wu)
{
    __shared__ float tile[32][33];
    const int z = blockIdx.z;
    const float* W = (z == 0) ? Wq : (z == 1) ? Wk : (z == 2) ? Wv : Wu;
    __nv_bfloat16* Bhi = (z < 3) ? g_Bqkv_hi : g_Bu_hi;
    __nv_bfloat16* Blo = (z < 3) ? g_Bqkv_lo : g_Bu_lo;
    const int nOff = (z < 3) ? z * 1024 : 0;

    const int tx = threadIdx.x, ty = threadIdx.y;
    const int n0 = blockIdx.x * 32, k0 = blockIdx.y * 32;
#pragma unroll
    for (int j = 0; j < 4; j++)
        tile[ty + j * 8][tx] = W[(size_t)(k0 + ty + j * 8) * Dn + n0 + tx];
    __syncthreads();
    const int kk = k0 + tx;
#pragma unroll
    for (int j = 0; j < 4; j++) {
        const int n = n0 + ty + j * 8;
        __nv_bfloat16 h, l;
        bsplit(tile[tx][ty + j * 8], h, l);
        Bhi[(size_t)(nOff + n) * Dn + kk] = h;
        Blo[(size_t)(nOff + n) * Dn + kk] = l;
    }
}

// ---------------------------------------------------------------------------
// HMMA GEMM, 2-stage pipeline, 2 CTAs/SM.
// MODE 1: scatter q/k/v as bf16 hi/lo head layout. MODE 0: d_out = D + bias.
// ---------------------------------------------------------------------------
template <int MODE>
__global__ void __launch_bounds__(256, 2)
hmma_gemm(const __nv_bfloat16* __restrict__ Ahi, const __nv_bfloat16* __restrict__ Alo,
          const __nv_bfloat16* __restrict__ Bhi, const __nv_bfloat16* __restrict__ Blo,
          const float* __restrict__ bias, float* __restrict__ Cout)
{
    extern __shared__ char smem[];
    const uint32_t sb = smem_u32(smem);
    const int t    = threadIdx.x;
    const int lane = t & 31;
    const int wid  = t >> 5;
    const int wm   = (wid & 1) << 6;
    const int wn   = (wid >> 1) << 5;
    const int m0   = blockIdx.y << 7;
    const int n0   = blockIdx.x << 7;

    auto load_stage = [&](int kc, int s) {
        const int kel = kc * BK;
        const uint32_t stb = sb + s * STG;
#pragma unroll
        for (int j = 0; j < 8; j++) {
            const int idx = t + (j << 8);
            const int mat = idx >> 9;
            const int rr  = (idx >> 2) & 127;
            const int cc  = idx & 3;
            const __nv_bfloat16* src;
            if (mat < 2)
                src = (mat ? Alo : Ahi) + (size_t)(m0 + rr) * Dn + kel + (cc << 3);
            else
                src = (mat == 2 ? Bhi : Blo) + (size_t)(n0 + rr) * Dn + kel + (cc << 3);
            cpa16(stb + mat * MATB + rr * ROWB + (cc << 4), src);
        }
        cpa_commit();
    };

    float acc[4][4][4];
#pragma unroll
    for (int i = 0; i < 4; i++)
#pragma unroll
        for (int j = 0; j < 4; j++)
#pragma unroll
            for (int q = 0; q < 4; q++) acc[i][j][q] = 0.f;

    load_stage(0, 0);

    for (int kc = 0; kc < NCHUNK; ++kc) {
        if (kc + 1 < NCHUNK) {
            load_stage(kc + 1, (kc + 1) & 1);
            cpa_wait<1>();
        } else {
            cpa_wait<0>();
        }
        __syncthreads();
        const uint32_t stb = sb + (kc & 1) * STG;

#pragma unroll
        for (int k16 = 0; k16 < 2; k16++) {
            uint32_t ah[16], al[16];
            const uint32_t abase = stb + (wm + (lane & 15)) * ROWB +
                                   (k16 << 5) + ((lane >> 4) << 4);
#pragma unroll
            for (int mt = 0; mt < 4; mt++) {
                ldm4(ah + 4 * mt, abase + mt * 16 * ROWB);
                ldm4(al + 4 * mt, abase + mt * 16 * ROWB + MATB);
            }
#pragma unroll
            for (int ng = 0; ng < 2; ng++) {
                uint32_t bh[4], bl[4];
                const uint32_t bbase = stb + 2 * MATB +
                                       (wn + ng * 16 + (lane & 15)) * ROWB +
                                       (k16 << 5) + ((lane >> 4) << 4);
                ldm4(bh, bbase);
                ldm4(bl, bbase + MATB);
#pragma unroll
                for (int mt = 0; mt < 4; mt++) {
#pragma unroll
                    for (int nn = 0; nn < 2; nn++) {
                        float* c = acc[mt][ng * 2 + nn];
                        const uint32_t b0  = nn ? bh[1] : bh[0];
                        const uint32_t b1  = nn ? bh[3] : bh[2];
                        const uint32_t lb0 = nn ? bl[1] : bl[0];
                        const uint32_t lb1 = nn ? bl[3] : bl[2];
                        mma16816(c, ah + 4 * mt, b0, b1);
                        mma16816(c, al + 4 * mt, b0, b1);
                        mma16816(c, ah + 4 * mt, lb0, lb1);
                    }
                }
            }
        }
        __syncthreads();
    }

    const int rbase = m0 + wm + (lane >> 2);
    const int cbase = (lane & 3) << 1;
#pragma unroll
    for (int mt = 0; mt < 4; mt++) {
#pragma unroll
        for (int nf = 0; nf < 4; nf++) {
            const int n = n0 + wn + ((nf >> 1) << 4) + ((nf & 1) << 3) + cbase;
            const float* c = acc[mt][nf];
#pragma unroll
            for (int half = 0; half < 2; half++) {
                const int r = rbase + mt * 16 + half * 8;
                const float v0 = c[2 * half], v1 = c[2 * half + 1];
                if (MODE == 0) {
                    *(float2*)&Cout[(size_t)r * Dn + n] =
                        make_float2(v0 + bias[n], v1 + bias[n + 1]);
                } else {
                    const int mat = n >> 10;
                    const int nn  = n & 1023;
                    const int h   = nn >> 6;
                    const int e   = nn & 63;
                    const int b   = r >> 12;
                    const int s   = r & (Sn - 1);
                    __nv_bfloat16* hi_arr =
                        (mat == 0) ? g_qhi : (mat == 1) ? g_khi : g_vhi;
                    __nv_bfloat16* lo_arr =
                        (mat == 0) ? g_qlo : (mat == 1) ? g_klo : g_vlo;
                    __nv_bfloat16 h0, h1, l0, l1;
                    bsplit(v0, h0, l0);
                    bsplit(v1, h1, l1);
                    const size_t off = ((size_t)(b * Hn + h) * Sn + s) * DHn + e;
                    __nv_bfloat162 p;
                    p.x = h0; p.y = h1; *(__nv_bfloat162*)&hi_arr[off] = p;
                    p.x = l0; p.y = l1; *(__nv_bfloat162*)&lo_arr[off] = p;
                }
            }
        }
    }
}

// ---------------------------------------------------------------------------
// Flash attention, warp-MMA (R6, unchanged).
// ---------------------------------------------------------------------------
__device__ __forceinline__ int kb_of(int jb, int kt, int& mtype, int& kc0) {
    mtype = 0; kc0 = 0;
    if (jb <= NGn) return kt * 64;
    if (jb == NBn - 1) return (kt < 2) ? kt * 64 : (Sn - 192 + (kt - 2) * 64);
    if (kt < 2) return kt * 64;
    mtype = 1; kc0 = (kt - 2) * 64;
    return (jb - 1) * 64 + (kt - 2) * 64;
}

__global__ void __launch_bounds__(128, 2)
attn_k(const float* __restrict__ to_mask,
       const float* __restrict__ band_mask,
       const float* __restrict__ from_mask)
{
    extern __shared__ char smem[];
    const uint32_t sb = smem_u32(smem);
    const int t = threadIdx.x, lane = t & 31, wid = t >> 5;
    const int idx = blockIdx.x;
    const int jb  = idx >> 5;
    const int bh  = idx & 31;
    const int b   = bh >> 4, h = bh & 15;
    const int wm  = wid << 4;

    const size_t hoff = (size_t)(b * Hn + h) * Sn * DHn;
    const __nv_bfloat16* qhg = g_qhi + hoff + (size_t)jb * 64 * DHn;
    const __nv_bfloat16* qlg = g_qlo + hoff + (size_t)jb * 64 * DHn;
    const __nv_bfloat16* khg = g_khi + hoff;
    const __nv_bfloat16* klg = g_klo + hoff;
    const __nv_bfloat16* vhg = g_vhi + hoff;
    const __nv_bfloat16* vlg = g_vlo + hoff;

#pragma unroll
    for (int j = 0; j < 8; j++) {
        const int i2 = t + (j << 7);
        const int mat = i2 >> 9;
        const int rr  = (i2 >> 3) & 63;
        const int cc  = i2 & 7;
        cpa16(sb + mat * AMAT + rr * AROW + (cc << 4),
              (mat ? qlg : qhg) + rr * DHn + (cc << 3));
    }
    cpa_commit();

    auto loadKV = [&](int kb, int s) {
        const uint32_t base = sb + AQ_BYTES + s * ASTAGE;
#pragma unroll
        for (int j = 0; j < 16; j++) {
            const int i2 = t + (j << 7);
            const int mat = i2 >> 9;
            const int rr  = (i2 >> 3) & 63;
            const int cc  = i2 & 7;
            const __nv_bfloat16* src =
                (mat == 0 ? khg : mat == 1 ? klg : mat == 2 ? vhg : vlg) +
                (size_t)(kb + rr) * DHn + (cc << 3);
            cpa16(base + mat * AMAT + rr * AROW + (cc << 4), src);
        }
        cpa_commit();
    };

    const int ntiles = (jb < NGn) ? 64 : 5;
    int mty, kc0_;
    loadKV(kb_of(jb, 0, mty, kc0_), 0);

    uint32_t qh[4][4], ql[4][4];
    float pv[8][4];
#pragma unroll
    for (int f = 0; f < 8; f++)
#pragma unroll
        for (int q = 0; q < 4; q++) pv[f][q] = 0.f;
    float mrow0 = -1e30f, mrow1 = -1e30f, lrow0 = 0.f, lrow1 = 0.f;

    const float rs = 0.125f;

    for (int kt = 0; kt < ntiles; ++kt) {
        if (kt + 1 < ntiles) {
            int mt2, kc2;
            loadKV(kb_of(jb, kt + 1, mt2, kc2), (kt + 1) & 1);
            cpa_wait<1>();
        } else {
            cpa_wait<0>();
        }
        __syncthreads();

        if (kt == 0) {
            const uint32_t qbase = sb + (wm + (lane & 15)) * AROW + ((lane >> 4) << 4);
#pragma unroll
            for (int ks = 0; ks < 4; ks++) {
                ldm4(qh[ks], qbase + (ks << 5));
                ldm4(ql[ks], qbase + (ks << 5) + AMAT);
            }
        }

        int mtype, kcol0;
        const int kb = kb_of(jb, kt, mtype, kcol0);
        const uint32_t SK = sb + AQ_BYTES + (kt & 1) * ASTAGE;
        const uint32_t SV = SK + 2 * AMAT;

        float sf[8][4];
#pragma unroll
        for (int f = 0; f < 8; f++)
#pragma unroll
            for (int q = 0; q < 4; q++) sf[f][q] = 0.f;
#pragma unroll
        for (int ks = 0; ks < 4; ks++) {
#pragma unroll
            for (int kg = 0; kg < 4; kg++) {
                uint32_t kh4[4], kl4[4];
                const uint32_t ka = SK + (kg * 16 + (lane & 15)) * AROW +
                                    (ks << 5) + ((lane >> 4) << 4);
                ldm4(kh4, ka);
                ldm4(kl4, ka + AMAT);
#pragma unroll
                for (int nn = 0; nn < 2; nn++) {
                    float* c = sf[kg * 2 + nn];
                    const uint32_t b0  = nn ? kh4[1] : kh4[0];
                    const uint32_t b1  = nn ? kh4[3] : kh4[2];
                    const uint32_t lb0 = nn ? kl4[1] : kl4[0];
                    const uint32_t lb1 = nn ? kl4[3] : kl4[2];
                    mma16816(c, qh[ks], b0, b1);
                    mma16816(c, ql[ks], b0, b1);
                    mma16816(c, qh[ks], lb0, lb1);
                }
            }
        }

        const int colb = (lane & 3) << 1;
        if (mtype == 0) {
#pragma unroll
            for (int f = 0; f < 8; f++) {
                const int key = kb + f * 8 + colb;
                const float p0 = (1.0f - to_mask[b * Sn + key]) * -10000.0f;
                const float p1 = (1.0f - to_mask[b * Sn + key + 1]) * -10000.0f;
                sf[f][0] = sf[f][0] * rs + p0;
                sf[f][1] = sf[f][1] * rs + p1;
                sf[f][2] = sf[f][2] * rs + p0;
                sf[f][3] = sf[f][3] * rs + p1;
            }
        } else {
            const int m_idx = jb - (NGn + 1);
            const int qi0 = wm + (lane >> 2);
            const float* bm0 = band_mask +
                ((size_t)(b * NMIDn + m_idx) * 64 + qi0) * 192 + kcol0 + colb;
#pragma unroll
            for (int f = 0; f < 8; f++) {
                sf[f][0] = sf[f][0] * rs + (1.0f - bm0[f * 8]) * -10000.0f;
                sf[f][1] = sf[f][1] * rs + (1.0f - bm0[f * 8 + 1]) * -10000.0f;
                sf[f][2] = sf[f][2] * rs + (1.0f - bm0[8 * 192 + f * 8]) * -10000.0f;
                sf[f][3] = sf[f][3] * rs + (1.0f - bm0[8 * 192 + f * 8 + 1]) * -10000.0f;
            }
        }

        float mx0 = -1e30f, mx1 = -1e30f;
#pragma unroll
        for (int f = 0; f < 8; f++) {
            mx0 = fmaxf(mx0, fmaxf(sf[f][0], sf[f][1]));
            mx1 = fmaxf(mx1, fmaxf(sf[f][2], sf[f][3]));
        }
        mx0 = fmaxf(mx0, __shfl_xor_sync(0xffffffffu, mx0, 1));
        mx0 = fmaxf(mx0, __shfl_xor_sync(0xffffffffu, mx0, 2));
        mx1 = fmaxf(mx1, __shfl_xor_sync(0xffffffffu, mx1, 1));
        mx1 = fmaxf(mx1, __shfl_xor_sync(0xffffffffu, mx1, 2));

        const float nm0 = fmaxf(mrow0, mx0), nm1 = fmaxf(mrow1, mx1);
        const float corr0 = __expf(mrow0 - nm0), corr1 = __expf(mrow1 - nm1);
        mrow0 = nm0; mrow1 = nm1;
        lrow0 *= corr0; lrow1 *= corr1;
#pragma unroll
        for (int f = 0; f < 8; f++) {
            pv[f][0] *= corr0; pv[f][1] *= corr0;
            pv[f][2] *= corr1; pv[f][3] *= corr1;
        }

        float rs0 = 0.f, rs1 = 0.f;
#pragma unroll
        for (int f = 0; f < 8; f++) {
            sf[f][0] = __expf(sf[f][0] - nm0);
            sf[f][1] = __expf(sf[f][1] - nm0);
            sf[f][2] = __expf(sf[f][2] - nm1);
            sf[f][3] = __expf(sf[f][3] - nm1);
            rs0 += sf[f][0] + sf[f][1];
            rs1 += sf[f][2] + sf[f][3];
        }
        rs0 += __shfl_xor_sync(0xffffffffu, rs0, 1);
        rs0 += __shfl_xor_sync(0xffffffffu, rs0, 2);
        rs1 += __shfl_xor_sync(0xffffffffu, rs1, 1);
        rs1 += __shfl_xor_sync(0xffffffffu, rs1, 2);
        lrow0 += rs0; lrow1 += rs1;

#pragma unroll
        for (int kg = 0; kg < 4; kg++) {
            uint32_t pa[4], pl[4];
            bsplit_pack(sf[2 * kg][0],     sf[2 * kg][1],     pa[0], pl[0]);
            bsplit_pack(sf[2 * kg][2],     sf[2 * kg][3],     pa[1], pl[1]);
            bsplit_pack(sf[2 * kg + 1][0], sf[2 * kg + 1][1], pa[2], pl[2]);
            bsplit_pack(sf[2 * kg + 1][2], sf[2 * kg + 1][3], pa[3], pl[3]);
#pragma unroll
            for (int eg = 0; eg < 4; eg++) {
                uint32_t vh4[4], vl4[4];
                const uint32_t va = SV +
                    (kg * 16 + (((lane >> 3) & 1) << 3) + (lane & 7)) * AROW +
                    (eg << 5) + ((lane >> 4) << 4);
                ldm4t(vh4, va);
                ldm4t(vl4, va + AMAT);
#pragma unroll
                for (int nn = 0; nn < 2; nn++) {
                    float* c = pv[eg * 2 + nn];
                    const uint32_t b0  = vh4[nn * 2];
                    const uint32_t b1  = vh4[nn * 2 + 1];
                    const uint32_t lb0 = vl4[nn * 2];
                    const uint32_t lb1 = vl4[nn * 2 + 1];
                    mma16816(c, pa, b0, b1);
                    mma16816(c, pl, b0, b1);
                    mma16816(c, pa, lb0, lb1);
                }
            }
        }
        __syncthreads();
    }

    const int srow0 = jb * 64 + wm + (lane >> 2);
    const int srow1 = srow0 + 8;
    const float sc0 = from_mask[b * Sn + srow0] / lrow0;
    const float sc1 = from_mask[b * Sn + srow1] / lrow1;
#pragma unroll
    for (int f = 0; f < 8; f++) {
        const int e = f * 8 + ((lane & 3) << 1);
        const size_t o0 = (size_t)(b * Sn + srow0) * Dn + h * 64 + e;
        const size_t o1 = (size_t)(b * Sn + srow1) * Dn + h * 64 + e;
        __nv_bfloat16 h0, h1, l0, l1;
        bsplit(pv[f][0] * sc0, h0, l0);
        bsplit(pv[f][1] * sc0, h1, l1);
        __nv_bfloat162 p;
        p.x = h0; p.y = h1; *(__nv_bfloat162*)&g_Chi[o0] = p;
        p.x = l0; p.y = l1; *(__nv_bfloat162*)&g_Clo[o0] = p;
        bsplit(pv[f][2] * sc1, h0, l0);
        bsplit(pv[f][3] * sc1, h1, l1);
        p.x = h0; p.y = h1; *(__nv_bfloat162*)&g_Chi[o1] = p;
        p.x = l0; p.y = l1; *(__nv_bfloat162*)&g_Clo[o1] = p;
    }
}

// ---------------------------------------------------------------------------
extern "C" void kernel_launch(void* const* d_in, const int* in_sizes, int n_in,
                              void* d_out, int out_size)
{
    const float* tokens    = (const float*)d_in[0];
    const float* band_mask = (const float*)d_in[1];
    const float* from_mask = (const float*)d_in[2];
    const float* to_mask   = (const float*)d_in[3];
    const float* Wq        = (const float*)d_in[4];
    const float* Wk        = (const float*)d_in[5];
    const float* Wv        = (const float*)d_in[6];
    const float* Wu        = (const float*)d_in[7];
    const float* bu        = (const float*)d_in[8];
    (void)in_sizes; (void)n_in; (void)out_size;

    __nv_bfloat16 *ahi, *alo, *bqh, *bql, *buh, *bul, *chi, *clo;
    cudaGetSymbolAddress((void**)&ahi, g_Ahi);
    cudaGetSymbolAddress((void**)&alo, g_Alo);
    cudaGetSymbolAddress((void**)&bqh, g_Bqkv_hi);
    cudaGetSymbolAddress((void**)&bql, g_Bqkv_lo);
    cudaGetSymbolAddress((void**)&buh, g_Bu_hi);
    cudaGetSymbolAddress((void**)&bul, g_Bu_lo);
    cudaGetSymbolAddress((void**)&chi, g_Chi);
    cudaGetSymbolAddress((void**)&clo, g_Clo);

    cudaFuncSetAttribute(attn_k, cudaFuncAttributeMaxDynamicSharedMemorySize, ATTN_SMEM);
    cudaFuncSetAttribute(hmma_gemm<0>, cudaFuncAttributeMaxDynamicSharedMemorySize, GEMM_SMEM);
    cudaFuncSetAttribute(hmma_gemm<1>, cudaFuncAttributeMaxDynamicSharedMemorySize, GEMM_SMEM);

    split_k<<<2048, 256>>>(tokens, ahi, alo, Mrows * Dn / 4);
    packW_all<<<dim3(32, 32, 4), dim3(32, 8)>>>(Wq, Wk, Wv, Wu);

    hmma_gemm<1><<<dim3(24, 64), 256, GEMM_SMEM>>>(ahi, alo, bqh, bql,
                                                   nullptr, nullptr);
    attn_k<<<Bn * Hn * NBn, 128, ATTN_SMEM>>>(to_mask, band_mask, from_mask);
    hmma_gemm<0><<<dim3(8, 64), 256, GEMM_SMEM>>>(chi, clo, buh, bul,
                                                  bu, (float*)d_out);
}

// round 8
// speedup vs baseline: 3.2231x; 1.2834x over previous
#include <cuda_runtime.h>
#include <cuda_fp16.h>
#include <cstdint>

// ---------------------------------------------------------------------------
// BigBird transformer block on sm_103 (non-'a' target: no tcgen05/TMEM).
// R8: fp16 mma.sync everywhere (11-bit mantissa vs bf16's 8).
//   - GEMMs: A split fp16 hi/lo, B single fp16 -> TWO products
//     (D = A.Bh exactly; dropped A.Bl ~2^-12 RMS). 33% fewer MMAs,
//     B-lo tile gone -> 30KB/stage -> 3-stage pipeline, 2 CTAs/SM.
//   - Attention: fp16 hi/lo, 3 products (error ~2^-22, adds nothing).
//   - 1/sqrt(d) folded into q at the QKV epilogue.
// ---------------------------------------------------------------------------

namespace {
constexpr int Bn    = 2;
constexpr int Sn    = 4096;
constexpr int Dn    = 1024;
constexpr int Hn    = 16;
constexpr int DHn   = 64;
constexpr int NBn   = 64;
constexpr int NGn   = 2;
constexpr int NMIDn = 60;
constexpr int Mrows = Bn * Sn;              // 8192

// GEMM tiling
constexpr int BK      = 32;
constexpr int NCHUNK  = Dn / BK;             // 32
constexpr int ROWB    = 80;                  // padded row bytes (32 fp16)
constexpr int MATB    = 128 * ROWB;          // 10240
constexpr int STG     = 3 * MATB;            // Ah, Al, Bh = 30720 B / stage
constexpr int GEMM_SMEM = 3 * STG;           // 92160 B -> 2 CTAs/SM

// attention smem
constexpr int AROW    = 144;
constexpr int AMAT    = 64 * AROW;           // 9216 B
constexpr int ASTAGE  = 4 * AMAT;            // Kh,Kl,Vh,Vl = 36864 B
constexpr int AQ_BYTES = 2 * AMAT;
constexpr int ATTN_SMEM = AQ_BYTES + 2 * ASTAGE;  // 92160 B
}

// ---- scratch (device globals) ----------------------------------------------
__device__ __half g_qhi[Bn * Hn * Sn * DHn], g_qlo[Bn * Hn * Sn * DHn];
__device__ __half g_khi[Bn * Hn * Sn * DHn], g_klo[Bn * Hn * Sn * DHn];
__device__ __half g_vhi[Bn * Hn * Sn * DHn], g_vlo[Bn * Hn * Sn * DHn];
__device__ __half g_Ahi[Mrows * Dn],  g_Alo[Mrows * Dn];
__device__ __half g_Bqkv_h[3 * Dn * Dn];
__device__ __half g_Bu_h[Dn * Dn];
__device__ __half g_Chi[Mrows * Dn],  g_Clo[Mrows * Dn];

// ---------------------------------------------------------------------------
// PTX helpers
// ---------------------------------------------------------------------------
__device__ __forceinline__ uint32_t smem_u32(const void* p) {
    uint32_t a;
    asm("{ .reg .u64 t; cvta.to.shared.u64 t, %1; cvt.u32.u64 %0, t; }" : "=r"(a) : "l"(p));
    return a;
}
__device__ __forceinline__ void cpa16(uint32_t dst, const void* src) {
    asm volatile("cp.async.cg.shared.global [%0], [%1], 16;" :: "r"(dst), "l"(src));
}
__device__ __forceinline__ void cpa_commit() {
    asm volatile("cp.async.commit_group;" ::: "memory");
}
template <int N>
__device__ __forceinline__ void cpa_wait() {
    asm volatile("cp.async.wait_group %0;" :: "n"(N) : "memory");
}
__device__ __forceinline__ void ldm4(uint32_t* r, uint32_t addr) {
    asm volatile("ldmatrix.sync.aligned.m8n8.x4.shared.b16 {%0,%1,%2,%3}, [%4];"
                 : "=r"(r[0]), "=r"(r[1]), "=r"(r[2]), "=r"(r[3]) : "r"(addr));
}
__device__ __forceinline__ void ldm4t(uint32_t* r, uint32_t addr) {
    asm volatile("ldmatrix.sync.aligned.m8n8.x4.trans.shared.b16 {%0,%1,%2,%3}, [%4];"
                 : "=r"(r[0]), "=r"(r[1]), "=r"(r[2]), "=r"(r[3]) : "r"(addr));
}
__device__ __forceinline__ void mma16816(float* c, const uint32_t* a,
                                         uint32_t b0, uint32_t b1) {
    asm volatile(
        "mma.sync.aligned.m16n8k16.row.col.f32.f16.f16.f32 "
        "{%0,%1,%2,%3}, {%4,%5,%6,%7}, {%8,%9}, {%0,%1,%2,%3};"
        : "+f"(c[0]), "+f"(c[1]), "+f"(c[2]), "+f"(c[3])
        : "r"(a[0]), "r"(a[1]), "r"(a[2]), "r"(a[3]), "r"(b0), "r"(b1));
}
__device__ __forceinline__ void hsplit(float v, __half& h, __half& l) {
    h = __float2half_rn(v);
    l = __float2half_rn(v - __half2float(h));
}
__device__ __forceinline__ void hsplit_pack(float v0, float v1,
                                            uint32_t& hp, uint32_t& lp) {
    __half2 h = __floats2half2_rn(v0, v1);
    __half2 l = __floats2half2_rn(v0 - __low2float(h), v1 - __high2float(h));
    hp = *reinterpret_cast<uint32_t*>(&h);
    lp = *reinterpret_cast<uint32_t*>(&l);
}

// ---------------------------------------------------------------------------
// prep kernels
// ---------------------------------------------------------------------------
__global__ void split_k(const float* __restrict__ X,
                        __half* __restrict__ Hi, __half* __restrict__ Lo, int n4)
{
    for (int i = blockIdx.x * blockDim.x + threadIdx.x; i < n4;
         i += gridDim.x * blockDim.x) {
        float4 v = ((const float4*)X)[i];
        __half2 h01 = __floats2half2_rn(v.x, v.y);
        __half2 h23 = __floats2half2_rn(v.z, v.w);
        __half2 l01 = __floats2half2_rn(v.x - __low2float(h01), v.y - __high2float(h01));
        __half2 l23 = __floats2half2_rn(v.z - __low2float(h23), v.w - __high2float(h23));
        *(__half2*)(Hi + 4 * i)     = h01;
        *(__half2*)(Hi + 4 * i + 2) = h23;
        *(__half2*)(Lo + 4 * i)     = l01;
        *(__half2*)(Lo + 4 * i + 2) = l23;
    }
}

// weight packs (transpose + fp16): z = 0..2 -> Wq/Wk/Wv into Bqkv, 3 -> Wu
__global__ void packW_all(const float* __restrict__ Wq, const float* __restrict__ Wk,
                          const float* __restrict__ Wv, const float* __restrict__ Wu)
{
    __shared__ float tile[32][33];
    const int z = blockIdx.z;
    const float* W = (z == 0) ? Wq : (z == 1) ? Wk : (z == 2) ? Wv : Wu;
    __half* Bh = (z < 3) ? g_Bqkv_h : g_Bu_h;
    const int nOff = (z < 3) ? z * 1024 : 0;

    const int tx = threadIdx.x, ty = threadIdx.y;
    const int n0 = blockIdx.x * 32, k0 = blockIdx.y * 32;
#pragma unroll
    for (int j = 0; j < 4; j++)
        tile[ty + j * 8][tx] = W[(size_t)(k0 + ty + j * 8) * Dn + n0 + tx];
    __syncthreads();
    const int kk = k0 + tx;
#pragma unroll
    for (int j = 0; j < 4; j++) {
        const int n = n0 + ty + j * 8;
        Bh[(size_t)(nOff + n) * Dn + kk] = __float2half_rn(tile[tx][ty + j * 8]);
    }
}

// ---------------------------------------------------------------------------
// fp16 HMMA GEMM, 2 products (Ah.Bh + Al.Bh), 3-stage pipeline, 2 CTAs/SM.
// MODE 1: scatter q/k/v as fp16 hi/lo head layout (q pre-scaled by 1/8).
// MODE 0: d_out = D + bias.
// ---------------------------------------------------------------------------
template <int MODE>
__global__ void __launch_bounds__(256, 2)
hmma_gemm(const __half* __restrict__ Ahi, const __half* __restrict__ Alo,
          const __half* __restrict__ Bh,
          const float* __restrict__ bias, float* __restrict__ Cout)
{
    extern __shared__ char smem[];
    const uint32_t sb = smem_u32(smem);
    const int t    = threadIdx.x;
    const int lane = t & 31;
    const int wid  = t >> 5;
    const int wm   = (wid & 1) << 6;
    const int wn   = (wid >> 1) << 5;
    const int m0   = blockIdx.y << 7;
    const int n0   = blockIdx.x << 7;

    auto load_stage = [&](int kc, int s) {
        const int kel = kc * BK;
        const uint32_t stb = sb + s * STG;
        // 3 mats x 128 rows x 4 chunks = 1536
#pragma unroll
        for (int j = 0; j < 6; j++) {
            const int idx = t + (j << 8);
            const int mat = idx >> 9;
            const int rr  = (idx >> 2) & 127;
            const int cc  = idx & 3;
            const __half* src;
            if (mat < 2)
                src = (mat ? Alo : Ahi) + (size_t)(m0 + rr) * Dn + kel + (cc << 3);
            else
                src = Bh + (size_t)(n0 + rr) * Dn + kel + (cc << 3);
            cpa16(stb + mat * MATB + rr * ROWB + (cc << 4), src);
        }
        cpa_commit();
    };

    float acc[4][4][4];
#pragma unroll
    for (int i = 0; i < 4; i++)
#pragma unroll
        for (int j = 0; j < 4; j++)
#pragma unroll
            for (int q = 0; q < 4; q++) acc[i][j][q] = 0.f;

    load_stage(0, 0);
    load_stage(1, 1);

    for (int kc = 0; kc < NCHUNK; ++kc) {
        if (kc + 2 < NCHUNK) { load_stage(kc + 2, (kc + 2) % 3); cpa_wait<2>(); }
        else if (kc + 1 < NCHUNK) cpa_wait<1>();
        else cpa_wait<0>();
        __syncthreads();
        const uint32_t stb = sb + (kc % 3) * STG;

#pragma unroll
        for (int k16 = 0; k16 < 2; k16++) {
            uint32_t ah[16], al[16];
            const uint32_t abase = stb + (wm + (lane & 15)) * ROWB +
                                   (k16 << 5) + ((lane >> 4) << 4);
#pragma unroll
            for (int mt = 0; mt < 4; mt++) {
                ldm4(ah + 4 * mt, abase + mt * 16 * ROWB);
                ldm4(al + 4 * mt, abase + mt * 16 * ROWB + MATB);
            }
#pragma unroll
            for (int ng = 0; ng < 2; ng++) {
                uint32_t bh4[4];
                const uint32_t bbase = stb + 2 * MATB +
                                       (wn + ng * 16 + (lane & 15)) * ROWB +
                                       (k16 << 5) + ((lane >> 4) << 4);
                ldm4(bh4, bbase);
#pragma unroll
                for (int mt = 0; mt < 4; mt++) {
#pragma unroll
                    for (int nn = 0; nn < 2; nn++) {
                        float* c = acc[mt][ng * 2 + nn];
                        const uint32_t b0 = nn ? bh4[1] : bh4[0];
                        const uint32_t b1 = nn ? bh4[3] : bh4[2];
                        mma16816(c, ah + 4 * mt, b0, b1);
                        mma16816(c, al + 4 * mt, b0, b1);
                    }
                }
            }
        }
        __syncthreads();
    }

    const int rbase = m0 + wm + (lane >> 2);
    const int cbase = (lane & 3) << 1;
#pragma unroll
    for (int mt = 0; mt < 4; mt++) {
#pragma unroll
        for (int nf = 0; nf < 4; nf++) {
            const int n = n0 + wn + ((nf >> 1) << 4) + ((nf & 1) << 3) + cbase;
            const float* c = acc[mt][nf];
#pragma unroll
            for (int half = 0; half < 2; half++) {
                const int r = rbase + mt * 16 + half * 8;
                float v0 = c[2 * half], v1 = c[2 * half + 1];
                if (MODE == 0) {
                    *(float2*)&Cout[(size_t)r * Dn + n] =
                        make_float2(v0 + bias[n], v1 + bias[n + 1]);
                } else {
                    const int mat = n >> 10;
                    const int nn  = n & 1023;
                    const int h   = nn >> 6;
                    const int e   = nn & 63;
                    const int b   = r >> 12;
                    const int s   = r & (Sn - 1);
                    if (mat == 0) { v0 *= 0.125f; v1 *= 0.125f; }  // fold 1/sqrt(d)
                    __half* hi_arr = (mat == 0) ? g_qhi : (mat == 1) ? g_khi : g_vhi;
                    __half* lo_arr = (mat == 0) ? g_qlo : (mat == 1) ? g_klo : g_vlo;
                    __half h0, h1, l0, l1;
                    hsplit(v0, h0, l0);
                    hsplit(v1, h1, l1);
                    const size_t off = ((size_t)(b * Hn + h) * Sn + s) * DHn + e;
                    *(__half2*)&hi_arr[off] = __halves2half2(h0, h1);
                    *(__half2*)&lo_arr[off] = __halves2half2(l0, l1);
                }
            }
        }
    }
}

// ---------------------------------------------------------------------------
// Flash attention, warp-MMA, fp16 hi/lo 3-product (structure as R6/R7).
// q arrives pre-scaled by 1/8.
// ---------------------------------------------------------------------------
__device__ __forceinline__ int kb_of(int jb, int kt, int& mtype, int& kc0) {
    mtype = 0; kc0 = 0;
    if (jb <= NGn) return kt * 64;
    if (jb == NBn - 1) return (kt < 2) ? kt * 64 : (Sn - 192 + (kt - 2) * 64);
    if (kt < 2) return kt * 64;
    mtype = 1; kc0 = (kt - 2) * 64;
    return (jb - 1) * 64 + (kt - 2) * 64;
}

__global__ void __launch_bounds__(128, 2)
attn_k(const float* __restrict__ to_mask,
       const float* __restrict__ band_mask,
       const float* __restrict__ from_mask)
{
    extern __shared__ char smem[];
    const uint32_t sb = smem_u32(smem);
    const int t = threadIdx.x, lane = t & 31, wid = t >> 5;
    const int idx = blockIdx.x;
    const int jb  = idx >> 5;
    const int bh  = idx & 31;
    const int b   = bh >> 4, h = bh & 15;
    const int wm  = wid << 4;

    const size_t hoff = (size_t)(b * Hn + h) * Sn * DHn;
    const __half* qhg = g_qhi + hoff + (size_t)jb * 64 * DHn;
    const __half* qlg = g_qlo + hoff + (size_t)jb * 64 * DHn;
    const __half* khg = g_khi + hoff;
    const __half* klg = g_klo + hoff;
    const __half* vhg = g_vhi + hoff;
    const __half* vlg = g_vlo + hoff;

#pragma unroll
    for (int j = 0; j < 8; j++) {
        const int i2 = t + (j << 7);
        const int mat = i2 >> 9;
        const int rr  = (i2 >> 3) & 63;
        const int cc  = i2 & 7;
        cpa16(sb + mat * AMAT + rr * AROW + (cc << 4),
              (mat ? qlg : qhg) + rr * DHn + (cc << 3));
    }
    cpa_commit();

    auto loadKV = [&](int kb, int s) {
        const uint32_t base = sb + AQ_BYTES + s * ASTAGE;
#pragma unroll
        for (int j = 0; j < 16; j++) {
            const int i2 = t + (j << 7);
            const int mat = i2 >> 9;
            const int rr  = (i2 >> 3) & 63;
            const int cc  = i2 & 7;
            const __half* src =
                (mat == 0 ? khg : mat == 1 ? klg : mat == 2 ? vhg : vlg) +
                (size_t)(kb + rr) * DHn + (cc << 3);
            cpa16(base + mat * AMAT + rr * AROW + (cc << 4), src);
        }
        cpa_commit();
    };

    const int ntiles = (jb < NGn) ? 64 : 5;
    int mty, kc0_;
    loadKV(kb_of(jb, 0, mty, kc0_), 0);

    uint32_t qh[4][4], ql[4][4];
    float pv[8][4];
#pragma unroll
    for (int f = 0; f < 8; f++)
#pragma unroll
        for (int q = 0; q < 4; q++) pv[f][q] = 0.f;
    float mrow0 = -1e30f, mrow1 = -1e30f, lrow0 = 0.f, lrow1 = 0.f;

    for (int kt = 0; kt < ntiles; ++kt) {
        if (kt + 1 < ntiles) {
            int mt2, kc2;
            loadKV(kb_of(jb, kt + 1, mt2, kc2), (kt + 1) & 1);
            cpa_wait<1>();
        } else {
            cpa_wait<0>();
        }
        __syncthreads();

        if (kt == 0) {
            const uint32_t qbase = sb + (wm + (lane & 15)) * AROW + ((lane >> 4) << 4);
#pragma unroll
            for (int ks = 0; ks < 4; ks++) {
                ldm4(qh[ks], qbase + (ks << 5));
                ldm4(ql[ks], qbase + (ks << 5) + AMAT);
            }
        }

        int mtype, kcol0;
        const int kb = kb_of(jb, kt, mtype, kcol0);
        const uint32_t SK = sb + AQ_BYTES + (kt & 1) * ASTAGE;
        const uint32_t SV = SK + 2 * AMAT;

        float sf[8][4];
#pragma unroll
        for (int f = 0; f < 8; f++)
#pragma unroll
            for (int q = 0; q < 4; q++) sf[f][q] = 0.f;
#pragma unroll
        for (int ks = 0; ks < 4; ks++) {
#pragma unroll
            for (int kg = 0; kg < 4; kg++) {
                uint32_t kh4[4], kl4[4];
                const uint32_t ka = SK + (kg * 16 + (lane & 15)) * AROW +
                                    (ks << 5) + ((lane >> 4) << 4);
                ldm4(kh4, ka);
                ldm4(kl4, ka + AMAT);
#pragma unroll
                for (int nn = 0; nn < 2; nn++) {
                    float* c = sf[kg * 2 + nn];
                    const uint32_t b0  = nn ? kh4[1] : kh4[0];
                    const uint32_t b1  = nn ? kh4[3] : kh4[2];
                    const uint32_t lb0 = nn ? kl4[1] : kl4[0];
                    const uint32_t lb1 = nn ? kl4[3] : kl4[2];
                    mma16816(c, qh[ks], b0, b1);
                    mma16816(c, ql[ks], b0, b1);
                    mma16816(c, qh[ks], lb0, lb1);
                }
            }
        }

        const int colb = (lane & 3) << 1;
        if (mtype == 0) {
#pragma unroll
            for (int f = 0; f < 8; f++) {
                const int key = kb + f * 8 + colb;
                const float p0 = (1.0f - to_mask[b * Sn + key]) * -10000.0f;
                const float p1 = (1.0f - to_mask[b * Sn + key + 1]) * -10000.0f;
                sf[f][0] += p0;
                sf[f][1] += p1;
                sf[f][2] += p0;
                sf[f][3] += p1;
            }
        } else {
            const int m_idx = jb - (NGn + 1);
            const int qi0 = wm + (lane >> 2);
            const float* bm0 = band_mask +
                ((size_t)(b * NMIDn + m_idx) * 64 + qi0) * 192 + kcol0 + colb;
#pragma unroll
            for (int f = 0; f < 8; f++) {
                sf[f][0] += (1.0f - bm0[f * 8]) * -10000.0f;
                sf[f][1] += (1.0f - bm0[f * 8 + 1]) * -10000.0f;
                sf[f][2] += (1.0f - bm0[8 * 192 + f * 8]) * -10000.0f;
                sf[f][3] += (1.0f - bm0[8 * 192 + f * 8 + 1]) * -10000.0f;
            }
        }

        float mx0 = -1e30f, mx1 = -1e30f;
#pragma unroll
        for (int f = 0; f < 8; f++) {
            mx0 = fmaxf(mx0, fmaxf(sf[f][0], sf[f][1]));
            mx1 = fmaxf(mx1, fmaxf(sf[f][2], sf[f][3]));
        }
        mx0 = fmaxf(mx0, __shfl_xor_sync(0xffffffffu, mx0, 1));
        mx0 = fmaxf(mx0, __shfl_xor_sync(0xffffffffu, mx0, 2));
        mx1 = fmaxf(mx1, __shfl_xor_sync(0xffffffffu, mx1, 1));
        mx1 = fmaxf(mx1, __shfl_xor_sync(0xffffffffu, mx1, 2));

        const float nm0 = fmaxf(mrow0, mx0), nm1 = fmaxf(mrow1, mx1);
        const float corr0 = __expf(mrow0 - nm0), corr1 = __expf(mrow1 - nm1);
        mrow0 = nm0; mrow1 = nm1;
        lrow0 *= corr0; lrow1 *= corr1;
#pragma unroll
        for (int f = 0; f < 8; f++) {
            pv[f][0] *= corr0; pv[f][1] *= corr0;
            pv[f][2] *= corr1; pv[f][3] *= corr1;
        }

        float rs0 = 0.f, rs1 = 0.f;
#pragma unroll
        for (int f = 0; f < 8; f++) {
            sf[f][0] = __expf(sf[f][0] - nm0);
            sf[f][1] = __expf(sf[f][1] - nm0);
            sf[f][2] = __expf(sf[f][2] - nm1);
            sf[f][3] = __expf(sf[f][3] - nm1);
            rs0 += sf[f][0] + sf[f][1];
            rs1 += sf[f][2] + sf[f][3];
        }
        rs0 += __shfl_xor_sync(0xffffffffu, rs0, 1);
        rs0 += __shfl_xor_sync(0xffffffffu, rs0, 2);
        rs1 += __shfl_xor_sync(0xffffffffu, rs1, 1);
        rs1 += __shfl_xor_sync(0xffffffffu, rs1, 2);
        lrow0 += rs0; lrow1 += rs1;

#pragma unroll
        for (int kg = 0; kg < 4; kg++) {
            uint32_t pa[4], pl[4];
            hsplit_pack(sf[2 * kg][0],     sf[2 * kg][1],     pa[0], pl[0]);
            hsplit_pack(sf[2 * kg][2],     sf[2 * kg][3],     pa[1], pl[1]);
            hsplit_pack(sf[2 * kg + 1][0], sf[2 * kg + 1][1], pa[2], pl[2]);
            hsplit_pack(sf[2 * kg + 1][2], sf[2 * kg + 1][3], pa[3], pl[3]);
#pragma unroll
            for (int eg = 0; eg < 4; eg++) {
                uint32_t vh4[4], vl4[4];
                const uint32_t va = SV +
                    (kg * 16 + (((lane >> 3) & 1) << 3) + (lane & 7)) * AROW +
                    (eg << 5) + ((lane >> 4) << 4);
                ldm4t(vh4, va);
                ldm4t(vl4, va + AMAT);
#pragma unroll
                for (int nn = 0; nn < 2; nn++) {
                    float* c = pv[eg * 2 + nn];
                    const uint32_t b0  = vh4[nn * 2];
                    const uint32_t b1  = vh4[nn * 2 + 1];
                    const uint32_t lb0 = vl4[nn * 2];
                    const uint32_t lb1 = vl4[nn * 2 + 1];
                    mma16816(c, pa, b0, b1);
                    mma16816(c, pl, b0, b1);
                    mma16816(c, pa, lb0, lb1);
                }
            }
        }
        __syncthreads();
    }

    const int srow0 = jb * 64 + wm + (lane >> 2);
    const int srow1 = srow0 + 8;
    const float sc0 = from_mask[b * Sn + srow0] / lrow0;
    const float sc1 = from_mask[b * Sn + srow1] / lrow1;
#pragma unroll
    for (int f = 0; f < 8; f++) {
        const int e = f * 8 + ((lane & 3) << 1);
        const size_t o0 = (size_t)(b * Sn + srow0) * Dn + h * 64 + e;
        const size_t o1 = (size_t)(b * Sn + srow1) * Dn + h * 64 + e;
        uint32_t hp, lp;
        hsplit_pack(pv[f][0] * sc0, pv[f][1] * sc0, hp, lp);
        *(uint32_t*)&g_Chi[o0] = hp;
        *(uint32_t*)&g_Clo[o0] = lp;
        hsplit_pack(pv[f][2] * sc1, pv[f][3] * sc1, hp, lp);
        *(uint32_t*)&g_Chi[o1] = hp;
        *(uint32_t*)&g_Clo[o1] = lp;
    }
}

// ---------------------------------------------------------------------------
extern "C" void kernel_launch(void* const* d_in, const int* in_sizes, int n_in,
                              void* d_out, int out_size)
{
    const float* tokens    = (const float*)d_in[0];
    const float* band_mask = (const float*)d_in[1];
    const float* from_mask = (const float*)d_in[2];
    const float* to_mask   = (const float*)d_in[3];
    const float* Wq        = (const float*)d_in[4];
    const float* Wk        = (const float*)d_in[5];
    const float* Wv        = (const float*)d_in[6];
    const float* Wu        = (const float*)d_in[7];
    const float* bu        = (const float*)d_in[8];
    (void)in_sizes; (void)n_in; (void)out_size;

    __half *ahi, *alo, *bqh, *buh, *chi, *clo;
    cudaGetSymbolAddress((void**)&ahi, g_Ahi);
    cudaGetSymbolAddress((void**)&alo, g_Alo);
    cudaGetSymbolAddress((void**)&bqh, g_Bqkv_h);
    cudaGetSymbolAddress((void**)&buh, g_Bu_h);
    cudaGetSymbolAddress((void**)&chi, g_Chi);
    cudaGetSymbolAddress((void**)&clo, g_Clo);

    cudaFuncSetAttribute(attn_k, cudaFuncAttributeMaxDynamicSharedMemorySize, ATTN_SMEM);
    cudaFuncSetAttribute(hmma_gemm<0>, cudaFuncAttributeMaxDynamicSharedMemorySize, GEMM_SMEM);
    cudaFuncSetAttribute(hmma_gemm<1>, cudaFuncAttributeMaxDynamicSharedMemorySize, GEMM_SMEM);

    split_k<<<2048, 256>>>(tokens, ahi, alo, Mrows * Dn / 4);
    packW_all<<<dim3(32, 32, 4), dim3(32, 8)>>>(Wq, Wk, Wv, Wu);

    hmma_gemm<1><<<dim3(24, 64), 256, GEMM_SMEM>>>(ahi, alo, bqh, nullptr, nullptr);
    attn_k<<<Bn * Hn * NBn, 128, ATTN_SMEM>>>(to_mask, band_mask, from_mask);
    hmma_gemm<0><<<dim3(8, 64), 256, GEMM_SMEM>>>(chi, clo, buh, bu, (float*)d_out);
}

// round 9
// speedup vs baseline: 3.2332x; 1.0031x over previous
#include <cuda_runtime.h>
#include <cuda_fp16.h>
#include <cstdint>

// ---------------------------------------------------------------------------
// BigBird transformer block on sm_103 (non-'a' target: no tcgen05/TMEM).
// R9: break dependent back-to-back MMA chains. All hi/lo product MMAs to the
// same accumulator were adjacent (asm volatile preserves order -> each pair
// serialized on HMMA latency). Reordered product-major so adjacent MMAs hit
// independent accumulators. Per-accumulator order unchanged -> results
// bitwise identical to R8.
// ---------------------------------------------------------------------------

namespace {
constexpr int Bn    = 2;
constexpr int Sn    = 4096;
constexpr int Dn    = 1024;
constexpr int Hn    = 16;
constexpr int DHn   = 64;
constexpr int NBn   = 64;
constexpr int NGn   = 2;
constexpr int NMIDn = 60;
constexpr int Mrows = Bn * Sn;              // 8192

// GEMM tiling
constexpr int BK      = 32;
constexpr int NCHUNK  = Dn / BK;             // 32
constexpr int ROWB    = 80;
constexpr int MATB    = 128 * ROWB;          // 10240
constexpr int STG     = 3 * MATB;            // 30720 B / stage
constexpr int GEMM_SMEM = 3 * STG;           // 92160 B -> 2 CTAs/SM

// attention smem
constexpr int AROW    = 144;
constexpr int AMAT    = 64 * AROW;           // 9216 B
constexpr int ASTAGE  = 4 * AMAT;            // 36864 B
constexpr int AQ_BYTES = 2 * AMAT;
constexpr int ATTN_SMEM = AQ_BYTES + 2 * ASTAGE;  // 92160 B
}

// ---- scratch (device globals) ----------------------------------------------
__device__ __half g_qhi[Bn * Hn * Sn * DHn], g_qlo[Bn * Hn * Sn * DHn];
__device__ __half g_khi[Bn * Hn * Sn * DHn], g_klo[Bn * Hn * Sn * DHn];
__device__ __half g_vhi[Bn * Hn * Sn * DHn], g_vlo[Bn * Hn * Sn * DHn];
__device__ __half g_Ahi[Mrows * Dn],  g_Alo[Mrows * Dn];
__device__ __half g_Bqkv_h[3 * Dn * Dn];
__device__ __half g_Bu_h[Dn * Dn];
__device__ __half g_Chi[Mrows * Dn],  g_Clo[Mrows * Dn];

// ---------------------------------------------------------------------------
// PTX helpers
// ---------------------------------------------------------------------------
__device__ __forceinline__ uint32_t smem_u32(const void* p) {
    uint32_t a;
    asm("{ .reg .u64 t; cvta.to.shared.u64 t, %1; cvt.u32.u64 %0, t; }" : "=r"(a) : "l"(p));
    return a;
}
__device__ __forceinline__ void cpa16(uint32_t dst, const void* src) {
    asm volatile("cp.async.cg.shared.global [%0], [%1], 16;" :: "r"(dst), "l"(src));
}
__device__ __forceinline__ void cpa_commit() {
    asm volatile("cp.async.commit_group;" ::: "memory");
}
template <int N>
__device__ __forceinline__ void cpa_wait() {
    asm volatile("cp.async.wait_group %0;" :: "n"(N) : "memory");
}
__device__ __forceinline__ void ldm4(uint32_t* r, uint32_t addr) {
    asm volatile("ldmatrix.sync.aligned.m8n8.x4.shared.b16 {%0,%1,%2,%3}, [%4];"
                 : "=r"(r[0]), "=r"(r[1]), "=r"(r[2]), "=r"(r[3]) : "r"(addr));
}
__device__ __forceinline__ void ldm4t(uint32_t* r, uint32_t addr) {
    asm volatile("ldmatrix.sync.aligned.m8n8.x4.trans.shared.b16 {%0,%1,%2,%3}, [%4];"
                 : "=r"(r[0]), "=r"(r[1]), "=r"(r[2]), "=r"(r[3]) : "r"(addr));
}
__device__ __forceinline__ void mma16816(float* c, const uint32_t* a,
                                         uint32_t b0, uint32_t b1) {
    asm volatile(
        "mma.sync.aligned.m16n8k16.row.col.f32.f16.f16.f32 "
        "{%0,%1,%2,%3}, {%4,%5,%6,%7}, {%8,%9}, {%0,%1,%2,%3};"
        : "+f"(c[0]), "+f"(c[1]), "+f"(c[2]), "+f"(c[3])
        : "r"(a[0]), "r"(a[1]), "r"(a[2]), "r"(a[3]), "r"(b0), "r"(b1));
}
__device__ __forceinline__ void hsplit(float v, __half& h, __half& l) {
    h = __float2half_rn(v);
    l = __float2half_rn(v - __half2float(h));
}
__device__ __forceinline__ void hsplit_pack(float v0, float v1,
                                            uint32_t& hp, uint32_t& lp) {
    __half2 h = __floats2half2_rn(v0, v1);
    __half2 l = __floats2half2_rn(v0 - __low2float(h), v1 - __high2float(h));
    hp = *reinterpret_cast<uint32_t*>(&h);
    lp = *reinterpret_cast<uint32_t*>(&l);
}

// ---------------------------------------------------------------------------
// prep kernels
// ---------------------------------------------------------------------------
__global__ void split_k(const float* __restrict__ X,
                        __half* __restrict__ Hi, __half* __restrict__ Lo, int n4)
{
    for (int i = blockIdx.x * blockDim.x + threadIdx.x; i < n4;
         i += gridDim.x * blockDim.x) {
        float4 v = ((const float4*)X)[i];
        __half2 h01 = __floats2half2_rn(v.x, v.y);
        __half2 h23 = __floats2half2_rn(v.z, v.w);
        __half2 l01 = __floats2half2_rn(v.x - __low2float(h01), v.y - __high2float(h01));
        __half2 l23 = __floats2half2_rn(v.z - __low2float(h23), v.w - __high2float(h23));
        *(__half2*)(Hi + 4 * i)     = h01;
        *(__half2*)(Hi + 4 * i + 2) = h23;
        *(__half2*)(Lo + 4 * i)     = l01;
        *(__half2*)(Lo + 4 * i + 2) = l23;
    }
}

__global__ void packW_all(const float* __restrict__ Wq, const float* __restrict__ Wk,
                          const float* __restrict__ Wv, const float* __restrict__ Wu)
{
    __shared__ float tile[32][33];
    const int z = blockIdx.z;
    const float* W = (z == 0) ? Wq : (z == 1) ? Wk : (z == 2) ? Wv : Wu;
    __half* Bh = (z < 3) ? g_Bqkv_h : g_Bu_h;
    const int nOff = (z < 3) ? z * 1024 : 0;

    const int tx = threadIdx.x, ty = threadIdx.y;
    const int n0 = blockIdx.x * 32, k0 = blockIdx.y * 32;
#pragma unroll
    for (int j = 0; j < 4; j++)
        tile[ty + j * 8][tx] = W[(size_t)(k0 + ty + j * 8) * Dn + n0 + tx];
    __syncthreads();
    const int kk = k0 + tx;
#pragma unroll
    for (int j = 0; j < 4; j++) {
        const int n = n0 + ty + j * 8;
        Bh[(size_t)(nOff + n) * Dn + kk] = __float2half_rn(tile[tx][ty + j * 8]);
    }
}

// ---------------------------------------------------------------------------
// fp16 HMMA GEMM, 2 products, 3-stage pipeline, 2 CTAs/SM.
// MMAs ordered product-major: adjacent MMAs hit independent accumulators.
// ---------------------------------------------------------------------------
template <int MODE>
__global__ void __launch_bounds__(256, 2)
hmma_gemm(const __half* __restrict__ Ahi, const __half* __restrict__ Alo,
          const __half* __restrict__ Bh,
          const float* __restrict__ bias, float* __restrict__ Cout)
{
    extern __shared__ char smem[];
    const uint32_t sb = smem_u32(smem);
    const int t    = threadIdx.x;
    const int lane = t & 31;
    const int wid  = t >> 5;
    const int wm   = (wid & 1) << 6;
    const int wn   = (wid >> 1) << 5;
    const int m0   = blockIdx.y << 7;
    const int n0   = blockIdx.x << 7;

    auto load_stage = [&](int kc, int s) {
        const int kel = kc * BK;
        const uint32_t stb = sb + s * STG;
#pragma unroll
        for (int j = 0; j < 6; j++) {
            const int idx = t + (j << 8);
            const int mat = idx >> 9;
            const int rr  = (idx >> 2) & 127;
            const int cc  = idx & 3;
            const __half* src;
            if (mat < 2)
                src = (mat ? Alo : Ahi) + (size_t)(m0 + rr) * Dn + kel + (cc << 3);
            else
                src = Bh + (size_t)(n0 + rr) * Dn + kel + (cc << 3);
            cpa16(stb + mat * MATB + rr * ROWB + (cc << 4), src);
        }
        cpa_commit();
    };

    float acc[4][4][4];
#pragma unroll
    for (int i = 0; i < 4; i++)
#pragma unroll
        for (int j = 0; j < 4; j++)
#pragma unroll
            for (int q = 0; q < 4; q++) acc[i][j][q] = 0.f;

    load_stage(0, 0);
    load_stage(1, 1);

    for (int kc = 0; kc < NCHUNK; ++kc) {
        if (kc + 2 < NCHUNK) { load_stage(kc + 2, (kc + 2) % 3); cpa_wait<2>(); }
        else if (kc + 1 < NCHUNK) cpa_wait<1>();
        else cpa_wait<0>();
        __syncthreads();
        const uint32_t stb = sb + (kc % 3) * STG;

#pragma unroll
        for (int k16 = 0; k16 < 2; k16++) {
            uint32_t ah[16], al[16];
            const uint32_t abase = stb + (wm + (lane & 15)) * ROWB +
                                   (k16 << 5) + ((lane >> 4) << 4);
#pragma unroll
            for (int mt = 0; mt < 4; mt++) {
                ldm4(ah + 4 * mt, abase + mt * 16 * ROWB);
                ldm4(al + 4 * mt, abase + mt * 16 * ROWB + MATB);
            }
#pragma unroll
            for (int ng = 0; ng < 2; ng++) {
                uint32_t bh4[4];
                const uint32_t bbase = stb + 2 * MATB +
                                       (wn + ng * 16 + (lane & 15)) * ROWB +
                                       (k16 << 5) + ((lane >> 4) << 4);
                ldm4(bh4, bbase);
                // pass 1: all ah products (8 independent accumulators)
#pragma unroll
                for (int mt = 0; mt < 4; mt++) {
#pragma unroll
                    for (int nn = 0; nn < 2; nn++) {
                        mma16816(acc[mt][ng * 2 + nn], ah + 4 * mt,
                                 nn ? bh4[1] : bh4[0], nn ? bh4[3] : bh4[2]);
                    }
                }
                // pass 2: all al products
#pragma unroll
                for (int mt = 0; mt < 4; mt++) {
#pragma unroll
                    for (int nn = 0; nn < 2; nn++) {
                        mma16816(acc[mt][ng * 2 + nn], al + 4 * mt,
                                 nn ? bh4[1] : bh4[0], nn ? bh4[3] : bh4[2]);
                    }
                }
            }
        }
        __syncthreads();
    }

    const int rbase = m0 + wm + (lane >> 2);
    const int cbase = (lane & 3) << 1;
#pragma unroll
    for (int mt = 0; mt < 4; mt++) {
#pragma unroll
        for (int nf = 0; nf < 4; nf++) {
            const int n = n0 + wn + ((nf >> 1) << 4) + ((nf & 1) << 3) + cbase;
            const float* c = acc[mt][nf];
#pragma unroll
            for (int half = 0; half < 2; half++) {
                const int r = rbase + mt * 16 + half * 8;
                float v0 = c[2 * half], v1 = c[2 * half + 1];
                if (MODE == 0) {
                    *(float2*)&Cout[(size_t)r * Dn + n] =
                        make_float2(v0 + bias[n], v1 + bias[n + 1]);
                } else {
                    const int mat = n >> 10;
                    const int nn  = n & 1023;
                    const int h   = nn >> 6;
                    const int e   = nn & 63;
                    const int b   = r >> 12;
                    const int s   = r & (Sn - 1);
                    if (mat == 0) { v0 *= 0.125f; v1 *= 0.125f; }
                    __half* hi_arr = (mat == 0) ? g_qhi : (mat == 1) ? g_khi : g_vhi;
                    __half* lo_arr = (mat == 0) ? g_qlo : (mat == 1) ? g_klo : g_vlo;
                    __half h0, h1, l0, l1;
                    hsplit(v0, h0, l0);
                    hsplit(v1, h1, l1);
                    const size_t off = ((size_t)(b * Hn + h) * Sn + s) * DHn + e;
                    *(__half2*)&hi_arr[off] = __halves2half2(h0, h1);
                    *(__half2*)&lo_arr[off] = __halves2half2(l0, l1);
                }
            }
        }
    }
}

// ---------------------------------------------------------------------------
// Flash attention, warp-MMA, fp16 hi/lo 3-product, product-major MMA order.
// ---------------------------------------------------------------------------
__device__ __forceinline__ int kb_of(int jb, int kt, int& mtype, int& kc0) {
    mtype = 0; kc0 = 0;
    if (jb <= NGn) return kt * 64;
    if (jb == NBn - 1) return (kt < 2) ? kt * 64 : (Sn - 192 + (kt - 2) * 64);
    if (kt < 2) return kt * 64;
    mtype = 1; kc0 = (kt - 2) * 64;
    return (jb - 1) * 64 + (kt - 2) * 64;
}

__global__ void __launch_bounds__(128, 2)
attn_k(const float* __restrict__ to_mask,
       const float* __restrict__ band_mask,
       const float* __restrict__ from_mask)
{
    extern __shared__ char smem[];
    const uint32_t sb = smem_u32(smem);
    const int t = threadIdx.x, lane = t & 31, wid = t >> 5;
    const int idx = blockIdx.x;
    const int jb  = idx >> 5;
    const int bh  = idx & 31;
    const int b   = bh >> 4, h = bh & 15;
    const int wm  = wid << 4;

    const size_t hoff = (size_t)(b * Hn + h) * Sn * DHn;
    const __half* qhg = g_qhi + hoff + (size_t)jb * 64 * DHn;
    const __half* qlg = g_qlo + hoff + (size_t)jb * 64 * DHn;
    const __half* khg = g_khi + hoff;
    const __half* klg = g_klo + hoff;
    const __half* vhg = g_vhi + hoff;
    const __half* vlg = g_vlo + hoff;

#pragma unroll
    for (int j = 0; j < 8; j++) {
        const int i2 = t + (j << 7);
        const int mat = i2 >> 9;
        const int rr  = (i2 >> 3) & 63;
        const int cc  = i2 & 7;
        cpa16(sb + mat * AMAT + rr * AROW + (cc << 4),
              (mat ? qlg : qhg) + rr * DHn + (cc << 3));
    }
    cpa_commit();

    auto loadKV = [&](int kb, int s) {
        const uint32_t base = sb + AQ_BYTES + s * ASTAGE;
#pragma unroll
        for (int j = 0; j < 16; j++) {
            const int i2 = t + (j << 7);
            const int mat = i2 >> 9;
            const int rr  = (i2 >> 3) & 63;
            const int cc  = i2 & 7;
            const __half* src =
                (mat == 0 ? khg : mat == 1 ? klg : mat == 2 ? vhg : vlg) +
                (size_t)(kb + rr) * DHn + (cc << 3);
            cpa16(base + mat * AMAT + rr * AROW + (cc << 4), src);
        }
        cpa_commit();
    };

    const int ntiles = (jb < NGn) ? 64 : 5;
    int mty, kc0_;
    loadKV(kb_of(jb, 0, mty, kc0_), 0);

    uint32_t qh[4][4], ql[4][4];
    float pv[8][4];
#pragma unroll
    for (int f = 0; f < 8; f++)
#pragma unroll
        for (int q = 0; q < 4; q++) pv[f][q] = 0.f;
    float mrow0 = -1e30f, mrow1 = -1e30f, lrow0 = 0.f, lrow1 = 0.f;

    for (int kt = 0; kt < ntiles; ++kt) {
        if (kt + 1 < ntiles) {
            int mt2, kc2;
            loadKV(kb_of(jb, kt + 1, mt2, kc2), (kt + 1) & 1);
            cpa_wait<1>();
        } else {
            cpa_wait<0>();
        }
        __syncthreads();

        if (kt == 0) {
            const uint32_t qbase = sb + (wm + (lane & 15)) * AROW + ((lane >> 4) << 4);
#pragma unroll
            for (int ks = 0; ks < 4; ks++) {
                ldm4(qh[ks], qbase + (ks << 5));
                ldm4(ql[ks], qbase + (ks << 5) + AMAT);
            }
        }

        int mtype, kcol0;
        const int kb = kb_of(jb, kt, mtype, kcol0);
        const uint32_t SK = sb + AQ_BYTES + (kt & 1) * ASTAGE;
        const uint32_t SV = SK + 2 * AMAT;

        float sf[8][4];
#pragma unroll
        for (int f = 0; f < 8; f++)
#pragma unroll
            for (int q = 0; q < 4; q++) sf[f][q] = 0.f;
#pragma unroll
        for (int ks = 0; ks < 4; ks++) {
#pragma unroll
            for (int kg = 0; kg < 4; kg++) {
                uint32_t kh4[4], kl4[4];
                const uint32_t ka = SK + (kg * 16 + (lane & 15)) * AROW +
                                    (ks << 5) + ((lane >> 4) << 4);
                ldm4(kh4, ka);
                ldm4(kl4, ka + AMAT);
                // product-major: adjacent MMAs -> different accumulators
#pragma unroll
                for (int nn = 0; nn < 2; nn++)
                    mma16816(sf[kg * 2 + nn], qh[ks],
                             nn ? kh4[1] : kh4[0], nn ? kh4[3] : kh4[2]);
#pragma unroll
                for (int nn = 0; nn < 2; nn++)
                    mma16816(sf[kg * 2 + nn], ql[ks],
                             nn ? kh4[1] : kh4[0], nn ? kh4[3] : kh4[2]);
#pragma unroll
                for (int nn = 0; nn < 2; nn++)
                    mma16816(sf[kg * 2 + nn], qh[ks],
                             nn ? kl4[1] : kl4[0], nn ? kl4[3] : kl4[2]);
            }
        }

        const int colb = (lane & 3) << 1;
        if (mtype == 0) {
#pragma unroll
            for (int f = 0; f < 8; f++) {
                const int key = kb + f * 8 + colb;
                const float p0 = (1.0f - to_mask[b * Sn + key]) * -10000.0f;
                const float p1 = (1.0f - to_mask[b * Sn + key + 1]) * -10000.0f;
                sf[f][0] += p0;
                sf[f][1] += p1;
                sf[f][2] += p0;
                sf[f][3] += p1;
            }
        } else {
            const int m_idx = jb - (NGn + 1);
            const int qi0 = wm + (lane >> 2);
            const float* bm0 = band_mask +
                ((size_t)(b * NMIDn + m_idx) * 64 + qi0) * 192 + kcol0 + colb;
#pragma unroll
            for (int f = 0; f < 8; f++) {
                sf[f][0] += (1.0f - bm0[f * 8]) * -10000.0f;
                sf[f][1] += (1.0f - bm0[f * 8 + 1]) * -10000.0f;
                sf[f][2] += (1.0f - bm0[8 * 192 + f * 8]) * -10000.0f;
                sf[f][3] += (1.0f - bm0[8 * 192 + f * 8 + 1]) * -10000.0f;
            }
        }

        float mx0 = -1e30f, mx1 = -1e30f;
#pragma unroll
        for (int f = 0; f < 8; f++) {
            mx0 = fmaxf(mx0, fmaxf(sf[f][0], sf[f][1]));
            mx1 = fmaxf(mx1, fmaxf(sf[f][2], sf[f][3]));
        }
        mx0 = fmaxf(mx0, __shfl_xor_sync(0xffffffffu, mx0, 1));
        mx0 = fmaxf(mx0, __shfl_xor_sync(0xffffffffu, mx0, 2));
        mx1 = fmaxf(mx1, __shfl_xor_sync(0xffffffffu, mx1, 1));
        mx1 = fmaxf(mx1, __shfl_xor_sync(0xffffffffu, mx1, 2));

        const float nm0 = fmaxf(mrow0, mx0), nm1 = fmaxf(mrow1, mx1);
        const float corr0 = __expf(mrow0 - nm0), corr1 = __expf(mrow1 - nm1);
        mrow0 = nm0; mrow1 = nm1;
        lrow0 *= corr0; lrow1 *= corr1;
#pragma unroll
        for (int f = 0; f < 8; f++) {
            pv[f][0] *= corr0; pv[f][1] *= corr0;
            pv[f][2] *= corr1; pv[f][3] *= corr1;
        }

        float rs0 = 0.f, rs1 = 0.f;
#pragma unroll
        for (int f = 0; f < 8; f++) {
            sf[f][0] = __expf(sf[f][0] - nm0);
            sf[f][1] = __expf(sf[f][1] - nm0);
            sf[f][2] = __expf(sf[f][2] - nm1);
            sf[f][3] = __expf(sf[f][3] - nm1);
            rs0 += sf[f][0] + sf[f][1];
            rs1 += sf[f][2] + sf[f][3];
        }
        rs0 += __shfl_xor_sync(0xffffffffu, rs0, 1);
        rs0 += __shfl_xor_sync(0xffffffffu, rs0, 2);
        rs1 += __shfl_xor_sync(0xffffffffu, rs1, 1);
        rs1 += __shfl_xor_sync(0xffffffffu, rs1, 2);
        lrow0 += rs0; lrow1 += rs1;

#pragma unroll
        for (int kg = 0; kg < 4; kg++) {
            uint32_t pa[4], pl[4];
            hsplit_pack(sf[2 * kg][0],     sf[2 * kg][1],     pa[0], pl[0]);
            hsplit_pack(sf[2 * kg][2],     sf[2 * kg][3],     pa[1], pl[1]);
            hsplit_pack(sf[2 * kg + 1][0], sf[2 * kg + 1][1], pa[2], pl[2]);
            hsplit_pack(sf[2 * kg + 1][2], sf[2 * kg + 1][3], pa[3], pl[3]);
#pragma unroll
            for (int eg = 0; eg < 4; eg++) {
                uint32_t vh4[4], vl4[4];
                const uint32_t va = SV +
                    (kg * 16 + (((lane >> 3) & 1) << 3) + (lane & 7)) * AROW +
                    (eg << 5) + ((lane >> 4) << 4);
                ldm4t(vh4, va);
                ldm4t(vl4, va + AMAT);
                // product-major over the two nn accumulators
#pragma unroll
                for (int nn = 0; nn < 2; nn++)
                    mma16816(pv[eg * 2 + nn], pa, vh4[nn * 2], vh4[nn * 2 + 1]);
#pragma unroll
                for (int nn = 0; nn < 2; nn++)
                    mma16816(pv[eg * 2 + nn], pl, vh4[nn * 2], vh4[nn * 2 + 1]);
#pragma unroll
                for (int nn = 0; nn < 2; nn++)
                    mma16816(pv[eg * 2 + nn], pa, vl4[nn * 2], vl4[nn * 2 + 1]);
            }
        }
        __syncthreads();
    }

    const int srow0 = jb * 64 + wm + (lane >> 2);
    const int srow1 = srow0 + 8;
    const float sc0 = from_mask[b * Sn + srow0] / lrow0;
    const float sc1 = from_mask[b * Sn + srow1] / lrow1;
#pragma unroll
    for (int f = 0; f < 8; f++) {
        const int e = f * 8 + ((lane & 3) << 1);
        const size_t o0 = (size_t)(b * Sn + srow0) * Dn + h * 64 + e;
        const size_t o1 = (size_t)(b * Sn + srow1) * Dn + h * 64 + e;
        uint32_t hp, lp;
        hsplit_pack(pv[f][0] * sc0, pv[f][1] * sc0, hp, lp);
        *(uint32_t*)&g_Chi[o0] = hp;
        *(uint32_t*)&g_Clo[o0] = lp;
        hsplit_pack(pv[f][2] * sc1, pv[f][3] * sc1, hp, lp);
        *(uint32_t*)&g_Chi[o1] = hp;
        *(uint32_t*)&g_Clo[o1] = lp;
    }
}

// ---------------------------------------------------------------------------
extern "C" void kernel_launch(void* const* d_in, const int* in_sizes, int n_in,
                              void* d_out, int out_size)
{
    const float* tokens    = (const float*)d_in[0];
    const float* band_mask = (const float*)d_in[1];
    const float* from_mask = (const float*)d_in[2];
    const float* to_mask   = (const float*)d_in[3];
    const float* Wq        = (const float*)d_in[4];
    const float* Wk        = (const float*)d_in[5];
    const float* Wv        = (const float*)d_in[6];
    const float* Wu        = (const float*)d_in[7];
    const float* bu        = (const float*)d_in[8];
    (void)in_sizes; (void)n_in; (void)out_size;

    __half *ahi, *alo, *bqh, *buh, *chi, *clo;
    cudaGetSymbolAddress((void**)&ahi, g_Ahi);
    cudaGetSymbolAddress((void**)&alo, g_Alo);
    cudaGetSymbolAddress((void**)&bqh, g_Bqkv_h);
    cudaGetSymbolAddress((void**)&buh, g_Bu_h);
    cudaGetSymbolAddress((void**)&chi, g_Chi);
    cudaGetSymbolAddress((void**)&clo, g_Clo);

    cudaFuncSetAttribute(attn_k, cudaFuncAttributeMaxDynamicSharedMemorySize, ATTN_SMEM);
    cudaFuncSetAttribute(hmma_gemm<0>, cudaFuncAttributeMaxDynamicSharedMemorySize, GEMM_SMEM);
    cudaFuncSetAttribute(hmma_gemm<1>, cudaFuncAttributeMaxDynamicSharedMemorySize, GEMM_SMEM);

    split_k<<<2048, 256>>>(tokens, ahi, alo, Mrows * Dn / 4);
    packW_all<<<dim3(32, 32, 4), dim3(32, 8)>>>(Wq, Wk, Wv, Wu);

    hmma_gemm<1><<<dim3(24, 64), 256, GEMM_SMEM>>>(ahi, alo, bqh, nullptr, nullptr);
    attn_k<<<Bn * Hn * NBn, 128, ATTN_SMEM>>>(to_mask, band_mask, from_mask);
    hmma_gemm<0><<<dim3(8, 64), 256, GEMM_SMEM>>>(chi, clo, buh, bu, (float*)d_out);
}